// round 2
// baseline (speedup 1.0000x reference)
#include <cuda_runtime.h>
#include <math.h>

// ---------------- problem constants ----------------
#define NB   512      // batch
#define NT   64       // time steps
#define ND   512      // model dim
#define NH   8        // heads
#define NDH  64       // head dim
#define NFF  2048     // ffn dim
#define NMOx 1040     // 2*D + 2*H
#define SCALE_ETA 0.125f  // DH^-0.5

// ---------------- device scratch (allocation-free rule: __device__ globals) ----------------
__device__ float  g_state[NB*NH*NDH*NDH];   // 64 MB recurrent state
__device__ float2 g_istats[NB*NT];          // LN stats per (b,t) item row
__device__ float2 g_lstats[NB];             // LN stats of last_item rows
__device__ float2 g_hstats[NB];             // LN stats of y1 rows (per step, reused)
__device__ float2 g_xstats[NB];             // LN stats of x rows (final)
__device__ float  g_usnorm[NB*ND];          // LN(user_static)
__device__ float  g_Q[NB*NT*ND];            // l2n(LN(item)@Wq) for all t (64 MB)
__device__ float  g_qlast[NB*ND];           // l2n(LN(last_item)@Wq)
__device__ float  g_mctx[NB*ND];            // memory read context (ping, reused per step)
__device__ float  g_y1[NB*ND];              // meta_in@mcW1 + mcb1 (raw, pre-LN)
__device__ float  g_mo[NB*NMOx];            // meta output
__device__ float  g_z[NB*NMOx];             // mod @ [Wk|Wv|Wa|We]
__device__ float  g_wkvae[ND*NMOx];         // concatenated weight
__device__ float  g_x[NB*ND];               // user_static + attn
__device__ float  g_a1[NB*NFF];             // relu(LN(x)@W1+b1)

// ---------------- small helper kernels ----------------

// per-row mean / rstd (jnp: var ddof=0, eps 1e-5)
__global__ void ln_stats_kernel(const float* __restrict__ x, float2* __restrict__ stats, int D) {
    int r = blockIdx.x;
    const float* row = x + (size_t)r * D;
    float s = 0.f, ss = 0.f;
    for (int i = threadIdx.x; i < D; i += blockDim.x) { float v = row[i]; s += v; ss = fmaf(v, v, ss); }
    for (int o = 16; o; o >>= 1) { s += __shfl_xor_sync(0xffffffffu, s, o); ss += __shfl_xor_sync(0xffffffffu, ss, o); }
    __shared__ float as[4], ass[4];
    int w = threadIdx.x >> 5, l = threadIdx.x & 31;
    if (l == 0) { as[w] = s; ass[w] = ss; }
    __syncthreads();
    if (threadIdx.x == 0) {
        s = as[0] + as[1] + as[2] + as[3];
        ss = ass[0] + ass[1] + ass[2] + ass[3];
        float mu = s / D;
        float var = ss / D - mu * mu;
        stats[r] = make_float2(mu, rsqrtf(var + 1e-5f));
    }
}

// full layernorm (stats + apply) for small row counts
__global__ void ln_full_kernel(const float* __restrict__ x, const float* __restrict__ g,
                               const float* __restrict__ bt, float* __restrict__ out, int D) {
    int r = blockIdx.x;
    const float* row = x + (size_t)r * D;
    float s = 0.f, ss = 0.f;
    for (int i = threadIdx.x; i < D; i += blockDim.x) { float v = row[i]; s += v; ss = fmaf(v, v, ss); }
    for (int o = 16; o; o >>= 1) { s += __shfl_xor_sync(0xffffffffu, s, o); ss += __shfl_xor_sync(0xffffffffu, ss, o); }
    __shared__ float as[4], ass[4];
    __shared__ float smu, srs;
    int w = threadIdx.x >> 5, l = threadIdx.x & 31;
    if (l == 0) { as[w] = s; ass[w] = ss; }
    __syncthreads();
    if (threadIdx.x == 0) {
        s = as[0] + as[1] + as[2] + as[3];
        ss = ass[0] + ass[1] + ass[2] + ass[3];
        float mu = s / D;
        float var = ss / D - mu * mu;
        smu = mu; srs = rsqrtf(var + 1e-5f);
    }
    __syncthreads();
    float mu = smu, rs = srs;
    for (int i = threadIdx.x; i < D; i += blockDim.x)
        out[(size_t)r * D + i] = (row[i] - mu) * rs * g[i] + bt[i];
}

// l2-normalize contiguous 64-element segments (one warp per segment)
__global__ void l2n_kernel(float* __restrict__ x, int nseg) {
    int w = (blockIdx.x * blockDim.x + threadIdx.x) >> 5;
    int lane = threadIdx.x & 31;
    if (w >= nseg) return;
    float* seg = x + ((size_t)w << 6);
    float a = seg[lane], c = seg[lane + 32];
    float ss = a * a + c * c;
    for (int o = 16; o; o >>= 1) ss += __shfl_xor_sync(0xffffffffu, ss, o);
    float inv = 1.f / fmaxf(sqrtf(ss), 1e-12f);
    seg[lane] = a * inv;
    seg[lane + 32] = c * inv;
}

// build [Wk | Wv | Wa | We] : [512, 1040]
__global__ void build_wkvae_kernel(const float* __restrict__ Wk, const float* __restrict__ Wv,
                                   const float* __restrict__ Wa, const float* __restrict__ We,
                                   float* __restrict__ W) {
    int idx = blockIdx.x * blockDim.x + threadIdx.x;
    const int total = ND * NMOx;
    for (; idx < total; idx += gridDim.x * blockDim.x) {
        int r = idx / NMOx, c = idx % NMOx;
        float v;
        if (c < 512)        v = Wk[r * 512 + c];
        else if (c < 1024)  v = Wv[r * 512 + (c - 512)];
        else if (c < 1032)  v = Wa[r * 8 + (c - 1024)];
        else                v = We[r * 8 + (c - 1032)];
        W[idx] = v;
    }
}

// ---------------- generic GEMM with fused A-operand transforms ----------------
// amode: 0=RAW, 1=LN, 2=LN+relu, 3=MOD (i_norm*(1+tanh(gamma))+beta), 4=CONCAT(us_norm|mctx)
// epimode: 0=none, 1=relu, 2=add addm
struct GemmP {
    const float*  A;   long lda;
    const float*  Bm;  long ldb;
    float*        C;   long ldc;
    int M, N, K;
    int amode;
    const float2* stats; long sstride;
    const float*  lng; const float* lnb;
    const float*  aux; long ldaux;
    const float*  bias;
    int epimode;
    const float*  addm; long ldadd;
};

__device__ __forceinline__ float a_elem(const GemmP& p, int r, int kk) {
    switch (p.amode) {
        case 0: return p.A[(size_t)r * p.lda + kk];
        case 1: case 2: {
            float2 s = p.stats[(size_t)r * p.sstride];
            float v = (p.A[(size_t)r * p.lda + kk] - s.x) * s.y * p.lng[kk] + p.lnb[kk];
            return (p.amode == 2) ? fmaxf(v, 0.f) : v;
        }
        case 3: {
            float2 s = p.stats[(size_t)r * p.sstride];
            float inorm = (p.A[(size_t)r * p.lda + kk] - s.x) * s.y * p.lng[kk] + p.lnb[kk];
            float gm = p.aux[(size_t)r * p.ldaux + kk];
            float bt = p.aux[(size_t)r * p.ldaux + 512 + kk];
            return inorm * (1.f + tanhf(gm)) + bt;
        }
        default: {  // 4: concat
            return (kk < 512) ? p.A[(size_t)r * p.lda + kk]
                              : p.aux[(size_t)r * p.ldaux + (kk - 512)];
        }
    }
}

// BM=32, BN=64, BK=16, 128 threads, 4x4 per thread
__global__ void gemm_kernel(GemmP p) {
    __shared__ float As[16][34];
    __shared__ float Bs[16][64];
    int tid = threadIdx.x;
    int n0 = blockIdx.x * 64;
    int row0 = blockIdx.y * 32;
    int tx = tid & 15;
    int ty = tid >> 4;
    float acc[4][4];
#pragma unroll
    for (int i = 0; i < 4; i++)
#pragma unroll
        for (int j = 0; j < 4; j++) acc[i][j] = 0.f;

    int nt = p.K >> 4;
    for (int t = 0; t < nt; t++) {
        int k0 = t << 4;
#pragma unroll
        for (int i = 0; i < 4; i++) {
            int idx = tid + (i << 7);
            int kk = idx & 15;
            int m = idx >> 4;
            As[kk][m] = a_elem(p, row0 + m, k0 + kk);
        }
#pragma unroll
        for (int i = 0; i < 8; i++) {
            int n = tid & 63;
            int kb = (tid >> 6) + (i << 1);
            int col = n0 + n;
            Bs[kb][n] = (col < p.N) ? p.Bm[(size_t)(k0 + kb) * p.ldb + col] : 0.f;
        }
        __syncthreads();
#pragma unroll
        for (int kk = 0; kk < 16; kk++) {
            float a0 = As[kk][ty * 4 + 0];
            float a1 = As[kk][ty * 4 + 1];
            float a2 = As[kk][ty * 4 + 2];
            float a3 = As[kk][ty * 4 + 3];
            float4 bv = *reinterpret_cast<const float4*>(&Bs[kk][tx << 2]);
            acc[0][0] = fmaf(a0, bv.x, acc[0][0]); acc[0][1] = fmaf(a0, bv.y, acc[0][1]);
            acc[0][2] = fmaf(a0, bv.z, acc[0][2]); acc[0][3] = fmaf(a0, bv.w, acc[0][3]);
            acc[1][0] = fmaf(a1, bv.x, acc[1][0]); acc[1][1] = fmaf(a1, bv.y, acc[1][1]);
            acc[1][2] = fmaf(a1, bv.z, acc[1][2]); acc[1][3] = fmaf(a1, bv.w, acc[1][3]);
            acc[2][0] = fmaf(a2, bv.x, acc[2][0]); acc[2][1] = fmaf(a2, bv.y, acc[2][1]);
            acc[2][2] = fmaf(a2, bv.z, acc[2][2]); acc[2][3] = fmaf(a2, bv.w, acc[2][3]);
            acc[3][0] = fmaf(a3, bv.x, acc[3][0]); acc[3][1] = fmaf(a3, bv.y, acc[3][1]);
            acc[3][2] = fmaf(a3, bv.z, acc[3][2]); acc[3][3] = fmaf(a3, bv.w, acc[3][3]);
        }
        __syncthreads();
    }
#pragma unroll
    for (int i = 0; i < 4; i++) {
        int r = row0 + ty * 4 + i;
#pragma unroll
        for (int j = 0; j < 4; j++) {
            int n = n0 + (tx << 2) + j;
            if (n < p.N) {
                float v = acc[i][j];
                if (p.bias) v += p.bias[n];
                if (p.epimode == 1) v = fmaxf(v, 0.f);
                else if (p.epimode == 2) v += p.addm[(size_t)r * p.ldadd + n];
                p.C[(size_t)r * p.ldc + n] = v;
            }
        }
    }
}

// ---------------- state kernels ----------------

__device__ __forceinline__ float dot16(const float4& s0, const float4& s1,
                                       const float4& s2, const float4& s3,
                                       const float* __restrict__ w) {
    float d = s0.x * w[0] + s0.y * w[1] + s0.z * w[2] + s0.w * w[3];
    d += s1.x * w[4] + s1.y * w[5] + s1.z * w[6] + s1.w * w[7];
    d += s2.x * w[8] + s2.y * w[9] + s2.z * w[10] + s2.w * w[11];
    d += s3.x * w[12] + s3.y * w[13] + s3.z * w[14] + s3.w * w[15];
    return d;
}

// mctx[b, h*64+i] = sum_j S[b,h,i,j] * q[b,h,j]  (initial read, state untouched)
__global__ void read_kernel(const float* __restrict__ state, const float* __restrict__ qbase,
                            long qstride, float* __restrict__ mctx) {
    int bh = blockIdx.x;
    int b = bh >> 3, h = bh & 7;
    __shared__ float sq[64];
    int tid = threadIdx.x;
    if (tid < 64) sq[tid] = qbase[(size_t)b * qstride + h * 64 + tid];
    __syncthreads();
    int row = tid >> 2, qd = tid & 3;
    const float* srow = state + ((size_t)bh << 12) + (row << 6) + (qd << 4);
    float4 s0 = *(const float4*)(srow + 0);
    float4 s1 = *(const float4*)(srow + 4);
    float4 s2 = *(const float4*)(srow + 8);
    float4 s3 = *(const float4*)(srow + 12);
    const float* qq = sq + (qd << 4);
    float d = dot16(s0, s1, s2, s3, qq);
    d += __shfl_xor_sync(0xffffffffu, d, 1);
    d += __shfl_xor_sync(0xffffffffu, d, 2);
    if (qd == 0) mctx[(size_t)b * ND + h * 64 + row] = d;
}

// per (b,h): normalize k, compute alpha/eta, pred = S*k, S = (1-a)S + eta*(v-pred)k^T,
// then mctx_next = S_new * q_next   (fused update + read of next step)
__global__ void update_kernel(const float* __restrict__ Z, const float* __restrict__ mo,
                              const float* __restrict__ ba, const float* __restrict__ be,
                              const float* __restrict__ qbase, long qstride,
                              float* __restrict__ state, float* __restrict__ mctx) {
    int bh = blockIdx.x;
    int b = bh >> 3, h = bh & 7;
    __shared__ float sk[64], sv[64], sq[64];
    __shared__ float snorm;
    int tid = threadIdx.x;
    const float* zrow = Z + (size_t)b * NMOx;
    if (tid < 64) {
        sk[tid] = zrow[h * 64 + tid];
        sv[tid] = zrow[512 + h * 64 + tid];
        sq[tid] = qbase[(size_t)b * qstride + h * 64 + tid];
    }
    __syncthreads();
    if (tid < 32) {
        float a = sk[tid], c = sk[tid + 32];
        float ss = a * a + c * c;
        for (int o = 16; o; o >>= 1) ss += __shfl_xor_sync(0xffffffffu, ss, o);
        if (tid == 0) snorm = fmaxf(sqrtf(ss), 1e-12f);
    }
    __syncthreads();
    float inv = 1.f / snorm;

    const float* morow = mo + (size_t)b * NMOx;
    float araw = zrow[1024 + h] + ba[h] + morow[1024 + h];
    float eraw = zrow[1032 + h] + be[h] + morow[1032 + h];
    float alpha = 1.f / (1.f + expf(-araw));
    float eta = (1.f / (1.f + expf(-eraw))) * SCALE_ETA;
    float om = 1.f - alpha;

    int row = tid >> 2, qd = tid & 3;
    float* srow = state + ((size_t)bh << 12) + (row << 6) + (qd << 4);
    float4 s0 = *(float4*)(srow + 0);
    float4 s1 = *(float4*)(srow + 4);
    float4 s2 = *(float4*)(srow + 8);
    float4 s3 = *(float4*)(srow + 12);
    const float* kq = sk + (qd << 4);
    const float* qq = sq + (qd << 4);

    float pred = dot16(s0, s1, s2, s3, kq) * inv;   // k normalized
    pred += __shfl_xor_sync(0xffffffffu, pred, 1);
    pred += __shfl_xor_sync(0xffffffffu, pred, 2);

    float coef = eta * (sv[row] - pred) * inv;      // coef applied to raw k

    s0.x = fmaf(coef, kq[0],  om * s0.x);  s0.y = fmaf(coef, kq[1],  om * s0.y);
    s0.z = fmaf(coef, kq[2],  om * s0.z);  s0.w = fmaf(coef, kq[3],  om * s0.w);
    s1.x = fmaf(coef, kq[4],  om * s1.x);  s1.y = fmaf(coef, kq[5],  om * s1.y);
    s1.z = fmaf(coef, kq[6],  om * s1.z);  s1.w = fmaf(coef, kq[7],  om * s1.w);
    s2.x = fmaf(coef, kq[8],  om * s2.x);  s2.y = fmaf(coef, kq[9],  om * s2.y);
    s2.z = fmaf(coef, kq[10], om * s2.z);  s2.w = fmaf(coef, kq[11], om * s2.w);
    s3.x = fmaf(coef, kq[12], om * s3.x);  s3.y = fmaf(coef, kq[13], om * s3.y);
    s3.z = fmaf(coef, kq[14], om * s3.z);  s3.w = fmaf(coef, kq[15], om * s3.w);

    *(float4*)(srow + 0) = s0;
    *(float4*)(srow + 4) = s1;
    *(float4*)(srow + 8) = s2;
    *(float4*)(srow + 12) = s3;

    float qdot = dot16(s0, s1, s2, s3, qq);
    qdot += __shfl_xor_sync(0xffffffffu, qdot, 1);
    qdot += __shfl_xor_sync(0xffffffffu, qdot, 2);
    if (qd == 0) mctx[(size_t)b * ND + h * 64 + row] = qdot;
}

// ---------------- host launcher ----------------

static void launch_gemm(const float* A, long lda, const float* Bm, long ldb, float* C, long ldc,
                        int M, int N, int K, int amode,
                        const float2* stats, long sstride, const float* lng, const float* lnb,
                        const float* aux, long ldaux, const float* bias, int epi,
                        const float* addm, long ldadd) {
    GemmP p;
    p.A = A; p.lda = lda; p.Bm = Bm; p.ldb = ldb; p.C = C; p.ldc = ldc;
    p.M = M; p.N = N; p.K = K; p.amode = amode;
    p.stats = stats; p.sstride = sstride; p.lng = lng; p.lnb = lnb;
    p.aux = aux; p.ldaux = ldaux; p.bias = bias; p.epimode = epi;
    p.addm = addm; p.ldadd = ldadd;
    dim3 grid((N + 63) / 64, M / 32);
    gemm_kernel<<<grid, 128>>>(p);
}

extern "C" void kernel_launch(void* const* d_in, const int* in_sizes, int n_in,
                              void* d_out, int out_size) {
    const float* item  = (const float*)d_in[0];   // [B,T,D]
    const float* ustat = (const float*)d_in[1];   // [B,D]
    const float* lastI = (const float*)d_in[2];   // [B,D]
    const float* init  = (const float*)d_in[3];   // [B,H,DH,DH]
    const float* Wq    = (const float*)d_in[4];
    const float* Wk    = (const float*)d_in[5];
    const float* Wv    = (const float*)d_in[6];
    const float* Wa    = (const float*)d_in[7];
    const float* ba    = (const float*)d_in[8];
    const float* We    = (const float*)d_in[9];
    const float* be    = (const float*)d_in[10];
    const float* mcW1  = (const float*)d_in[11];  // [1024,512]
    const float* mcb1  = (const float*)d_in[12];
    const float* mcg   = (const float*)d_in[13];
    const float* mcbt  = (const float*)d_in[14];
    const float* mcW2  = (const float*)d_in[15];  // [512,1040]
    const float* mcb2  = (const float*)d_in[16];
    const float* Wo    = (const float*)d_in[17];
    const float* bo    = (const float*)d_in[18];
    const float* W1    = (const float*)d_in[19];  // [512,2048]
    const float* b1    = (const float*)d_in[20];
    const float* W2    = (const float*)d_in[21];  // [2048,512]
    const float* b2    = (const float*)d_in[22];
    const float* n1g   = (const float*)d_in[23];
    const float* n1b   = (const float*)d_in[24];
    const float* n2g   = (const float*)d_in[25];
    const float* n2b   = (const float*)d_in[26];
    float* out = (float*)d_out;

    float *state, *usnorm, *Q, *qlast, *mctx, *y1, *mov, *z, *wkvae, *x, *a1;
    float2 *istats, *lstats, *hstats, *xstats;
    cudaGetSymbolAddress((void**)&state,  g_state);
    cudaGetSymbolAddress((void**)&istats, g_istats);
    cudaGetSymbolAddress((void**)&lstats, g_lstats);
    cudaGetSymbolAddress((void**)&hstats, g_hstats);
    cudaGetSymbolAddress((void**)&xstats, g_xstats);
    cudaGetSymbolAddress((void**)&usnorm, g_usnorm);
    cudaGetSymbolAddress((void**)&Q,      g_Q);
    cudaGetSymbolAddress((void**)&qlast,  g_qlast);
    cudaGetSymbolAddress((void**)&mctx,   g_mctx);
    cudaGetSymbolAddress((void**)&y1,     g_y1);
    cudaGetSymbolAddress((void**)&mov,    g_mo);
    cudaGetSymbolAddress((void**)&z,      g_z);
    cudaGetSymbolAddress((void**)&wkvae,  g_wkvae);
    cudaGetSymbolAddress((void**)&x,      g_x);
    cudaGetSymbolAddress((void**)&a1,     g_a1);

    // ---- preamble ----
    cudaMemcpyAsync(state, init, (size_t)NB * NH * NDH * NDH * sizeof(float),
                    cudaMemcpyDeviceToDevice);
    ln_stats_kernel<<<NB * NT, 128>>>(item, istats, ND);
    ln_full_kernel<<<NB, 128>>>(ustat, n1g, n1b, usnorm, ND);
    ln_stats_kernel<<<NB, 128>>>(lastI, lstats, ND);
    build_wkvae_kernel<<<2080, 256>>>(Wk, Wv, Wa, We, wkvae);

    // Q for all (b,t): LN(item) @ Wq, then l2n per head
    launch_gemm(item, ND, Wq, ND, Q, ND, NB * NT, ND, ND, /*LN*/1,
                istats, 1, n1g, n1b, nullptr, 0, nullptr, 0, nullptr, 0);
    // q_last: LN(last_item) @ Wq, l2n per head
    launch_gemm(lastI, ND, Wq, ND, qlast, ND, NB, ND, ND, /*LN*/1,
                lstats, 1, n1g, n1b, nullptr, 0, nullptr, 0, nullptr, 0);
    l2n_kernel<<<(NB * NT * NH) / 8, 256>>>(Q, NB * NT * NH);
    l2n_kernel<<<(NB * NH) / 8, 256>>>(qlast, NB * NH);

    // initial read: mctx = S_init * q_0
    read_kernel<<<NB * NH, 256>>>(state, Q, (long)NT * ND, mctx);

    // ---- recurrence ----
    for (int t = 0; t < NT; t++) {
        // y1 = [us_norm | mctx] @ mcW1 + mcb1
        launch_gemm(usnorm, ND, mcW1, ND, y1, ND, NB, ND, 2 * ND, /*CONCAT*/4,
                    nullptr, 0, nullptr, nullptr, mctx, ND, mcb1, 0, nullptr, 0);
        ln_stats_kernel<<<NB, 128>>>(y1, hstats, ND);
        // mo = relu(LN(y1)) @ mcW2 + mcb2
        launch_gemm(y1, ND, mcW2, NMOx, mov, NMOx, NB, NMOx, ND, /*LNRELU*/2,
                    hstats, 1, mcg, mcbt, nullptr, 0, mcb2, 0, nullptr, 0);
        // Z = mod @ [Wk|Wv|Wa|We]; mod computed on the fly from item_t, istats, mo
        launch_gemm(item + (size_t)t * ND, (long)NT * ND, wkvae, NMOx, z, NMOx,
                    NB, NMOx, ND, /*MOD*/3,
                    istats + t, NT, n1g, n1b, mov, NMOx, nullptr, 0, nullptr, 0);
        // state update + read context for next step (or final read via q_last at t=63)
        const float* qn = (t < NT - 1) ? (Q + (size_t)(t + 1) * ND) : qlast;
        long qstride = (t < NT - 1) ? (long)NT * ND : (long)ND;
        update_kernel<<<NB * NH, 256>>>(z, mov, ba, be, qn, qstride, state, mctx);
    }

    // ---- readout + FFN ----
    // x = user_static + (mctx @ Wo + bo)
    launch_gemm(mctx, ND, Wo, ND, x, ND, NB, ND, ND, /*RAW*/0,
                nullptr, 0, nullptr, nullptr, nullptr, 0, bo, /*ADD*/2, ustat, ND);
    ln_stats_kernel<<<NB, 128>>>(x, xstats, ND);
    // a1 = relu(LN(x) @ W1 + b1)
    launch_gemm(x, ND, W1, NFF, a1, NFF, NB, NFF, ND, /*LN*/1,
                xstats, 1, n2g, n2b, nullptr, 0, b1, /*RELU*/1, nullptr, 0);
    // out = x + (a1 @ W2 + b2)
    launch_gemm(a1, NFF, W2, ND, out, ND, NB, ND, NFF, /*RAW*/0,
                nullptr, 0, nullptr, nullptr, nullptr, 0, b2, /*ADD*/2, x, ND);
}

// round 3
// speedup vs baseline: 1.2003x; 1.2003x over previous
#include <cuda_runtime.h>
#include <math.h>
#include <stdint.h>

// ---------------- problem constants ----------------
#define NB   512      // batch
#define NT   64       // time steps
#define ND   512      // model dim
#define NH   8        // heads
#define NDH  64       // head dim
#define NFF  2048     // ffn dim
#define NMOx 1040     // 2*D + 2*H
#define SCALE_ETA 0.125f  // DH^-0.5

// ---------------- device scratch ----------------
__device__ float  g_state[NB*NH*NDH*NDH];   // 64 MB recurrent state
__device__ float2 g_istats[NB*NT];
__device__ float2 g_lstats[NB];
__device__ float2 g_hstats[NB];
__device__ float2 g_xstats[NB];
__device__ float  g_usnorm[NB*ND];
__device__ float  g_Q[NB*NT*ND];
__device__ float  g_qlast[NB*ND];
__device__ float  g_mctx[NB*ND];
__device__ float  g_y1[NB*ND];
__device__ float  g_mo[NB*NMOx];
__device__ float  g_mod[NB*ND];
__device__ float  g_z[NB*NMOx];
__device__ float  g_wkvae[ND*NMOx];
__device__ float  g_x[NB*ND];
__device__ float  g_a1[NB*NFF];

// ---------------- small helper kernels ----------------

__global__ void ln_stats_kernel(const float* __restrict__ x, float2* __restrict__ stats, int D) {
    int r = blockIdx.x;
    const float* row = x + (size_t)r * D;
    float s = 0.f, ss = 0.f;
    for (int i = threadIdx.x; i < D; i += blockDim.x) { float v = row[i]; s += v; ss = fmaf(v, v, ss); }
    for (int o = 16; o; o >>= 1) { s += __shfl_xor_sync(0xffffffffu, s, o); ss += __shfl_xor_sync(0xffffffffu, ss, o); }
    __shared__ float as[4], ass[4];
    int w = threadIdx.x >> 5, l = threadIdx.x & 31;
    if (l == 0) { as[w] = s; ass[w] = ss; }
    __syncthreads();
    if (threadIdx.x == 0) {
        s = as[0] + as[1] + as[2] + as[3];
        ss = ass[0] + ass[1] + ass[2] + ass[3];
        float mu = s / D;
        float var = ss / D - mu * mu;
        stats[r] = make_float2(mu, rsqrtf(var + 1e-5f));
    }
}

__global__ void ln_full_kernel(const float* __restrict__ x, const float* __restrict__ g,
                               const float* __restrict__ bt, float* __restrict__ out, int D) {
    int r = blockIdx.x;
    const float* row = x + (size_t)r * D;
    float s = 0.f, ss = 0.f;
    for (int i = threadIdx.x; i < D; i += blockDim.x) { float v = row[i]; s += v; ss = fmaf(v, v, ss); }
    for (int o = 16; o; o >>= 1) { s += __shfl_xor_sync(0xffffffffu, s, o); ss += __shfl_xor_sync(0xffffffffu, ss, o); }
    __shared__ float as[4], ass[4];
    __shared__ float smu, srs;
    int w = threadIdx.x >> 5, l = threadIdx.x & 31;
    if (l == 0) { as[w] = s; ass[w] = ss; }
    __syncthreads();
    if (threadIdx.x == 0) {
        s = as[0] + as[1] + as[2] + as[3];
        ss = ass[0] + ass[1] + ass[2] + ass[3];
        float mu = s / D;
        float var = ss / D - mu * mu;
        smu = mu; srs = rsqrtf(var + 1e-5f);
    }
    __syncthreads();
    float mu = smu, rs = srs;
    for (int i = threadIdx.x; i < D; i += blockDim.x)
        out[(size_t)r * D + i] = (row[i] - mu) * rs * g[i] + bt[i];
}

__global__ void l2n_kernel(float* __restrict__ x, int nseg) {
    int w = (blockIdx.x * blockDim.x + threadIdx.x) >> 5;
    int lane = threadIdx.x & 31;
    if (w >= nseg) return;
    float* seg = x + ((size_t)w << 6);
    float a = seg[lane], c = seg[lane + 32];
    float ss = a * a + c * c;
    for (int o = 16; o; o >>= 1) ss += __shfl_xor_sync(0xffffffffu, ss, o);
    float inv = 1.f / fmaxf(sqrtf(ss), 1e-12f);
    seg[lane] = a * inv;
    seg[lane + 32] = c * inv;
}

__global__ void build_wkvae_kernel(const float* __restrict__ Wk, const float* __restrict__ Wv,
                                   const float* __restrict__ Wa, const float* __restrict__ We,
                                   float* __restrict__ W) {
    int idx = blockIdx.x * blockDim.x + threadIdx.x;
    const int total = ND * NMOx;
    for (; idx < total; idx += gridDim.x * blockDim.x) {
        int r = idx / NMOx, c = idx % NMOx;
        float v;
        if (c < 512)        v = Wk[r * 512 + c];
        else if (c < 1024)  v = Wv[r * 512 + (c - 512)];
        else if (c < 1032)  v = Wa[r * 8 + (c - 1024)];
        else                v = We[r * 8 + (c - 1032)];
        W[idx] = v;
    }
}

// mod[b][d] = i_norm * (1 + tanh(gamma)) + beta   (hoists tanh out of GEMM A-loader)
__global__ void mod_kernel(const float* __restrict__ item_t, const float2* __restrict__ istats_t,
                           const float* __restrict__ mo, const float* __restrict__ n1g,
                           const float* __restrict__ n1b, float* __restrict__ mod) {
    int idx = blockIdx.x * blockDim.x + threadIdx.x;
    if (idx >= NB * ND) return;
    int b = idx >> 9, d = idx & 511;
    float2 s = istats_t[(size_t)b * NT];
    float inorm = (item_t[(size_t)b * NT * ND + d] - s.x) * s.y * n1g[d] + n1b[d];
    float gm = mo[(size_t)b * NMOx + d];
    float bt = mo[(size_t)b * NMOx + 512 + d];
    mod[idx] = inorm * (1.f + tanhf(gm)) + bt;
}

// ---------------- tf32 tensor-core GEMM with fused A-operand transforms ----------------
// amode: 0=RAW, 1=LN, 2=LN+relu, 4=CONCAT(us_norm|mctx)
// epimode: 0=none, 1=relu, 2=add addm
struct GemmP {
    const float*  A;   long lda;
    const float*  Bm;  long ldb;
    float*        C;   long ldc;
    int M, N, K;
    int amode;
    const float2* stats; long sstride;
    const float*  lng; const float* lnb;
    const float*  aux; long ldaux;
    const float*  bias;
    int epimode;
    const float*  addm; long ldadd;
};

__device__ __forceinline__ float a_elem(const GemmP& p, int r, int kk) {
    switch (p.amode) {
        case 0: return p.A[(size_t)r * p.lda + kk];
        case 1: case 2: {
            float2 s = p.stats[(size_t)r * p.sstride];
            float v = (p.A[(size_t)r * p.lda + kk] - s.x) * s.y * p.lng[kk] + p.lnb[kk];
            return (p.amode == 2) ? fmaxf(v, 0.f) : v;
        }
        default: {  // 4: concat
            return (kk < 512) ? p.A[(size_t)r * p.lda + kk]
                              : p.aux[(size_t)r * p.ldaux + (kk - 512)];
        }
    }
}

__device__ __forceinline__ float tf32r(float x) {
    uint32_t u;
    asm("cvt.rna.tf32.f32 %0, %1;" : "=r"(u) : "f"(x));
    return __uint_as_float(u);
}

__device__ __forceinline__ void mma_tf32(float* c, const uint32_t* a, const uint32_t* b) {
    asm volatile(
        "mma.sync.aligned.m16n8k8.row.col.f32.tf32.tf32.f32 "
        "{%0,%1,%2,%3},{%4,%5,%6,%7},{%8,%9},{%0,%1,%2,%3};"
        : "+f"(c[0]), "+f"(c[1]), "+f"(c[2]), "+f"(c[3])
        : "r"(a[0]), "r"(a[1]), "r"(a[2]), "r"(a[3]), "r"(b[0]), "r"(b[1]));
}

// BM=64, BN=64, BK=32, 128 threads (4 warps, 2x2), warp tile 32x32 via m16n8k8
__global__ void gemm_tf32_kernel(GemmP p) {
    __shared__ float As[32 * 65];   // [k][m], pad 65 -> conflict-free STS, 2-way LDS
    __shared__ float Bs[32 * 65];   // [k][n]
    int tid = threadIdx.x;
    int warp = tid >> 5, lane = tid & 31;
    int g = lane >> 2, tig = lane & 3;
    int wm = (warp >> 1) * 32;
    int wn = (warp & 1) * 32;
    int row0 = blockIdx.y * 64;
    int n0 = blockIdx.x * 64;

    float acc[2][4][4];
#pragma unroll
    for (int mt = 0; mt < 2; mt++)
#pragma unroll
        for (int nt = 0; nt < 4; nt++)
#pragma unroll
            for (int e = 0; e < 4; e++) acc[mt][nt][e] = 0.f;

    int nkt = p.K >> 5;
    for (int kt = 0; kt < nkt; kt++) {
        int k0 = kt << 5;
        // A: 64x32 (coalesced by k), stored [k][m]
#pragma unroll
        for (int i = 0; i < 16; i++) {
            int idx = i * 128 + tid;
            int m = idx >> 5, k = idx & 31;
            As[k * 65 + m] = tf32r(a_elem(p, row0 + m, k0 + k));
        }
        // B: 32x64 (coalesced by n), stored [k][n]
#pragma unroll
        for (int i = 0; i < 16; i++) {
            int idx = i * 128 + tid;
            int k = idx >> 6, n = idx & 63;
            int col = n0 + n;
            float v = (col < p.N) ? p.Bm[(size_t)(k0 + k) * p.ldb + col] : 0.f;
            Bs[k * 65 + n] = tf32r(v);
        }
        __syncthreads();
#pragma unroll
        for (int ks = 0; ks < 4; ks++) {
            int k8 = ks * 8;
            uint32_t a[2][4], b[4][2];
#pragma unroll
            for (int mt = 0; mt < 2; mt++) {
                int mb = wm + mt * 16 + g;
                a[mt][0] = __float_as_uint(As[(k8 + tig) * 65 + mb]);
                a[mt][1] = __float_as_uint(As[(k8 + tig) * 65 + mb + 8]);
                a[mt][2] = __float_as_uint(As[(k8 + tig + 4) * 65 + mb]);
                a[mt][3] = __float_as_uint(As[(k8 + tig + 4) * 65 + mb + 8]);
            }
#pragma unroll
            for (int nt = 0; nt < 4; nt++) {
                int nb = wn + nt * 8 + g;
                b[nt][0] = __float_as_uint(Bs[(k8 + tig) * 65 + nb]);
                b[nt][1] = __float_as_uint(Bs[(k8 + tig + 4) * 65 + nb]);
            }
#pragma unroll
            for (int mt = 0; mt < 2; mt++)
#pragma unroll
                for (int nt = 0; nt < 4; nt++)
                    mma_tf32(acc[mt][nt], a[mt], b[nt]);
        }
        __syncthreads();
    }

    // epilogue
#pragma unroll
    for (int mt = 0; mt < 2; mt++) {
#pragma unroll
        for (int nt = 0; nt < 4; nt++) {
#pragma unroll
            for (int e = 0; e < 4; e++) {
                int r = row0 + wm + mt * 16 + g + ((e >= 2) ? 8 : 0);
                int c = n0 + wn + nt * 8 + tig * 2 + (e & 1);
                if (c < p.N) {
                    float v = acc[mt][nt][e];
                    if (p.bias) v += p.bias[c];
                    if (p.epimode == 1) v = fmaxf(v, 0.f);
                    else if (p.epimode == 2) v += p.addm[(size_t)r * p.ldadd + c];
                    p.C[(size_t)r * p.ldc + c] = v;
                }
            }
        }
    }
}

// ---------------- state kernels (exact fp32) ----------------

__device__ __forceinline__ float dot16(const float4& s0, const float4& s1,
                                       const float4& s2, const float4& s3,
                                       const float* __restrict__ w) {
    float d = s0.x * w[0] + s0.y * w[1] + s0.z * w[2] + s0.w * w[3];
    d += s1.x * w[4] + s1.y * w[5] + s1.z * w[6] + s1.w * w[7];
    d += s2.x * w[8] + s2.y * w[9] + s2.z * w[10] + s2.w * w[11];
    d += s3.x * w[12] + s3.y * w[13] + s3.z * w[14] + s3.w * w[15];
    return d;
}

__global__ void read_kernel(const float* __restrict__ state, const float* __restrict__ qbase,
                            long qstride, float* __restrict__ mctx) {
    int bh = blockIdx.x;
    int b = bh >> 3, h = bh & 7;
    __shared__ float sq[64];
    int tid = threadIdx.x;
    if (tid < 64) sq[tid] = qbase[(size_t)b * qstride + h * 64 + tid];
    __syncthreads();
    int row = tid >> 2, qd = tid & 3;
    const float* srow = state + ((size_t)bh << 12) + (row << 6) + (qd << 4);
    float4 s0 = *(const float4*)(srow + 0);
    float4 s1 = *(const float4*)(srow + 4);
    float4 s2 = *(const float4*)(srow + 8);
    float4 s3 = *(const float4*)(srow + 12);
    const float* qq = sq + (qd << 4);
    float d = dot16(s0, s1, s2, s3, qq);
    d += __shfl_xor_sync(0xffffffffu, d, 1);
    d += __shfl_xor_sync(0xffffffffu, d, 2);
    if (qd == 0) mctx[(size_t)b * ND + h * 64 + row] = d;
}

__global__ void update_kernel(const float* __restrict__ Z, const float* __restrict__ mo,
                              const float* __restrict__ ba, const float* __restrict__ be,
                              const float* __restrict__ qbase, long qstride,
                              float* __restrict__ state, float* __restrict__ mctx) {
    int bh = blockIdx.x;
    int b = bh >> 3, h = bh & 7;
    __shared__ float sk[64], sv[64], sq[64];
    __shared__ float snorm;
    int tid = threadIdx.x;
    const float* zrow = Z + (size_t)b * NMOx;
    if (tid < 64) {
        sk[tid] = zrow[h * 64 + tid];
        sv[tid] = zrow[512 + h * 64 + tid];
        sq[tid] = qbase[(size_t)b * qstride + h * 64 + tid];
    }
    __syncthreads();
    if (tid < 32) {
        float a = sk[tid], c = sk[tid + 32];
        float ss = a * a + c * c;
        for (int o = 16; o; o >>= 1) ss += __shfl_xor_sync(0xffffffffu, ss, o);
        if (tid == 0) snorm = fmaxf(sqrtf(ss), 1e-12f);
    }
    __syncthreads();
    float inv = 1.f / snorm;

    const float* morow = mo + (size_t)b * NMOx;
    float araw = zrow[1024 + h] + ba[h] + morow[1024 + h];
    float eraw = zrow[1032 + h] + be[h] + morow[1032 + h];
    float alpha = 1.f / (1.f + expf(-araw));
    float eta = (1.f / (1.f + expf(-eraw))) * SCALE_ETA;
    float om = 1.f - alpha;

    int row = tid >> 2, qd = tid & 3;
    float* srow = state + ((size_t)bh << 12) + (row << 6) + (qd << 4);
    float4 s0 = *(float4*)(srow + 0);
    float4 s1 = *(float4*)(srow + 4);
    float4 s2 = *(float4*)(srow + 8);
    float4 s3 = *(float4*)(srow + 12);
    const float* kq = sk + (qd << 4);
    const float* qq = sq + (qd << 4);

    float pred = dot16(s0, s1, s2, s3, kq) * inv;
    pred += __shfl_xor_sync(0xffffffffu, pred, 1);
    pred += __shfl_xor_sync(0xffffffffu, pred, 2);

    float coef = eta * (sv[row] - pred) * inv;

    s0.x = fmaf(coef, kq[0],  om * s0.x);  s0.y = fmaf(coef, kq[1],  om * s0.y);
    s0.z = fmaf(coef, kq[2],  om * s0.z);  s0.w = fmaf(coef, kq[3],  om * s0.w);
    s1.x = fmaf(coef, kq[4],  om * s1.x);  s1.y = fmaf(coef, kq[5],  om * s1.y);
    s1.z = fmaf(coef, kq[6],  om * s1.z);  s1.w = fmaf(coef, kq[7],  om * s1.w);
    s2.x = fmaf(coef, kq[8],  om * s2.x);  s2.y = fmaf(coef, kq[9],  om * s2.y);
    s2.z = fmaf(coef, kq[10], om * s2.z);  s2.w = fmaf(coef, kq[11], om * s2.w);
    s3.x = fmaf(coef, kq[12], om * s3.x);  s3.y = fmaf(coef, kq[13], om * s3.y);
    s3.z = fmaf(coef, kq[14], om * s3.z);  s3.w = fmaf(coef, kq[15], om * s3.w);

    *(float4*)(srow + 0) = s0;
    *(float4*)(srow + 4) = s1;
    *(float4*)(srow + 8) = s2;
    *(float4*)(srow + 12) = s3;

    float qdot = dot16(s0, s1, s2, s3, qq);
    qdot += __shfl_xor_sync(0xffffffffu, qdot, 1);
    qdot += __shfl_xor_sync(0xffffffffu, qdot, 2);
    if (qd == 0) mctx[(size_t)b * ND + h * 64 + row] = qdot;
}

// ---------------- host launcher ----------------

static void launch_gemm(const float* A, long lda, const float* Bm, long ldb, float* C, long ldc,
                        int M, int N, int K, int amode,
                        const float2* stats, long sstride, const float* lng, const float* lnb,
                        const float* aux, long ldaux, const float* bias, int epi,
                        const float* addm, long ldadd) {
    GemmP p;
    p.A = A; p.lda = lda; p.Bm = Bm; p.ldb = ldb; p.C = C; p.ldc = ldc;
    p.M = M; p.N = N; p.K = K; p.amode = amode;
    p.stats = stats; p.sstride = sstride; p.lng = lng; p.lnb = lnb;
    p.aux = aux; p.ldaux = ldaux; p.bias = bias; p.epimode = epi;
    p.addm = addm; p.ldadd = ldadd;
    dim3 grid((N + 63) / 64, M / 64);
    gemm_tf32_kernel<<<grid, 128>>>(p);
}

extern "C" void kernel_launch(void* const* d_in, const int* in_sizes, int n_in,
                              void* d_out, int out_size) {
    const float* item  = (const float*)d_in[0];
    const float* ustat = (const float*)d_in[1];
    const float* lastI = (const float*)d_in[2];
    const float* init  = (const float*)d_in[3];
    const float* Wq    = (const float*)d_in[4];
    const float* Wk    = (const float*)d_in[5];
    const float* Wv    = (const float*)d_in[6];
    const float* Wa    = (const float*)d_in[7];
    const float* ba    = (const float*)d_in[8];
    const float* We    = (const float*)d_in[9];
    const float* be    = (const float*)d_in[10];
    const float* mcW1  = (const float*)d_in[11];
    const float* mcb1  = (const float*)d_in[12];
    const float* mcg   = (const float*)d_in[13];
    const float* mcbt  = (const float*)d_in[14];
    const float* mcW2  = (const float*)d_in[15];
    const float* mcb2  = (const float*)d_in[16];
    const float* Wo    = (const float*)d_in[17];
    const float* bo    = (const float*)d_in[18];
    const float* W1    = (const float*)d_in[19];
    const float* b1    = (const float*)d_in[20];
    const float* W2    = (const float*)d_in[21];
    const float* b2    = (const float*)d_in[22];
    const float* n1g   = (const float*)d_in[23];
    const float* n1b   = (const float*)d_in[24];
    const float* n2g   = (const float*)d_in[25];
    const float* n2b   = (const float*)d_in[26];
    float* out = (float*)d_out;

    float *state, *usnorm, *Q, *qlast, *mctx, *y1, *mov, *modb, *z, *wkvae, *x, *a1;
    float2 *istats, *lstats, *hstats, *xstats;
    cudaGetSymbolAddress((void**)&state,  g_state);
    cudaGetSymbolAddress((void**)&istats, g_istats);
    cudaGetSymbolAddress((void**)&lstats, g_lstats);
    cudaGetSymbolAddress((void**)&hstats, g_hstats);
    cudaGetSymbolAddress((void**)&xstats, g_xstats);
    cudaGetSymbolAddress((void**)&usnorm, g_usnorm);
    cudaGetSymbolAddress((void**)&Q,      g_Q);
    cudaGetSymbolAddress((void**)&qlast,  g_qlast);
    cudaGetSymbolAddress((void**)&mctx,   g_mctx);
    cudaGetSymbolAddress((void**)&y1,     g_y1);
    cudaGetSymbolAddress((void**)&mov,    g_mo);
    cudaGetSymbolAddress((void**)&modb,   g_mod);
    cudaGetSymbolAddress((void**)&z,      g_z);
    cudaGetSymbolAddress((void**)&wkvae,  g_wkvae);
    cudaGetSymbolAddress((void**)&x,      g_x);
    cudaGetSymbolAddress((void**)&a1,     g_a1);

    // ---- preamble ----
    cudaMemcpyAsync(state, init, (size_t)NB * NH * NDH * NDH * sizeof(float),
                    cudaMemcpyDeviceToDevice);
    ln_stats_kernel<<<NB * NT, 128>>>(item, istats, ND);
    ln_full_kernel<<<NB, 128>>>(ustat, n1g, n1b, usnorm, ND);
    ln_stats_kernel<<<NB, 128>>>(lastI, lstats, ND);
    build_wkvae_kernel<<<2080, 256>>>(Wk, Wv, Wa, We, wkvae);

    // Q for all (b,t): LN(item) @ Wq, then l2n per head
    launch_gemm(item, ND, Wq, ND, Q, ND, NB * NT, ND, ND, /*LN*/1,
                istats, 1, n1g, n1b, nullptr, 0, nullptr, 0, nullptr, 0);
    launch_gemm(lastI, ND, Wq, ND, qlast, ND, NB, ND, ND, /*LN*/1,
                lstats, 1, n1g, n1b, nullptr, 0, nullptr, 0, nullptr, 0);
    l2n_kernel<<<(NB * NT * NH) / 8, 256>>>(Q, NB * NT * NH);
    l2n_kernel<<<(NB * NH) / 8, 256>>>(qlast, NB * NH);

    // initial read: mctx = S_init * q_0
    read_kernel<<<NB * NH, 256>>>(state, Q, (long)NT * ND, mctx);

    // ---- recurrence ----
    for (int t = 0; t < NT; t++) {
        // y1 = [us_norm | mctx] @ mcW1 + mcb1
        launch_gemm(usnorm, ND, mcW1, ND, y1, ND, NB, ND, 2 * ND, /*CONCAT*/4,
                    nullptr, 0, nullptr, nullptr, mctx, ND, mcb1, 0, nullptr, 0);
        ln_stats_kernel<<<NB, 128>>>(y1, hstats, ND);
        // mo = relu(LN(y1)) @ mcW2 + mcb2
        launch_gemm(y1, ND, mcW2, NMOx, mov, NMOx, NB, NMOx, ND, /*LNRELU*/2,
                    hstats, 1, mcg, mcbt, nullptr, 0, mcb2, 0, nullptr, 0);
        // mod = i_norm * (1 + tanh(gamma)) + beta  (precompute once, tanh hoisted)
        mod_kernel<<<(NB * ND + 255) / 256, 256>>>(item + (size_t)t * ND, istats + t,
                                                   mov, n1g, n1b, modb);
        // Z = mod @ [Wk|Wv|Wa|We]
        launch_gemm(modb, ND, wkvae, NMOx, z, NMOx, NB, NMOx, ND, /*RAW*/0,
                    nullptr, 0, nullptr, nullptr, nullptr, 0, nullptr, 0, nullptr, 0);
        // state update + fused read of next step's context
        const float* qn = (t < NT - 1) ? (Q + (size_t)(t + 1) * ND) : qlast;
        long qstride = (t < NT - 1) ? (long)NT * ND : (long)ND;
        update_kernel<<<NB * NH, 256>>>(z, mov, ba, be, qn, qstride, state, mctx);
    }

    // ---- readout + FFN ----
    launch_gemm(mctx, ND, Wo, ND, x, ND, NB, ND, ND, /*RAW*/0,
                nullptr, 0, nullptr, nullptr, nullptr, 0, bo, /*ADD*/2, ustat, ND);
    ln_stats_kernel<<<NB, 128>>>(x, xstats, ND);
    launch_gemm(x, ND, W1, NFF, a1, NFF, NB, NFF, ND, /*LN*/1,
                xstats, 1, n2g, n2b, nullptr, 0, b1, /*RELU*/1, nullptr, 0);
    launch_gemm(a1, NFF, W2, ND, out, ND, NB, ND, NFF, /*RAW*/0,
                nullptr, 0, nullptr, nullptr, nullptr, 0, b2, /*ADD*/2, x, ND);
}

// round 5
// speedup vs baseline: 1.7187x; 1.4318x over previous
#include <cuda_runtime.h>
#include <math.h>
#include <stdint.h>

// ---------------- problem constants ----------------
#define NB   512
#define NT   64
#define ND   512
#define NH   8
#define NDH  64
#define NFF  2048
#define NMOx 1040
#define SCALE_ETA 0.125f
#define NBLK 148          // persistent grid (<= 152 SMs on GB300, co-resident wave 1)
#define NTHR 512
#define NWG  (NBLK * 4)   // 592 warpgroup workers

// per-warpgroup smem: As 32x33 + Bs 32x65 floats
#define WG_SMEM_FLOATS (32 * 33 + 32 * 65)   // 3136
#define SMEM_BYTES (4 * WG_SMEM_FLOATS * 4)  // 50176

// ---------------- device scratch ----------------
__device__ float  g_state[NB*NH*NDH*NDH];
__device__ float2 g_istats[NB*NT];
__device__ float2 g_lstats[NB];
__device__ float2 g_hstats[NB];
__device__ float2 g_xstats[NB];
__device__ float  g_usnorm[NB*ND];
__device__ float  g_Q[NB*NT*ND];
__device__ float  g_qlast[NB*ND];
__device__ float  g_mctx[NB*ND];
__device__ float  g_y1a[NB*ND];
__device__ float  g_y1b[NB*ND];
__device__ float  g_y1[NB*ND];
__device__ float  g_mo[NB*NMOx];
__device__ float  g_mod[NB*ND];
__device__ float  g_z[NB*NMOx];
__device__ float  g_wkvae[ND*NMOx];
__device__ float  g_x[NB*ND];
__device__ float  g_a1[NB*NFF];
__device__ unsigned g_bar_count = 0;
__device__ unsigned g_bar_gen   = 0;

// ---------------- small helper kernels (preamble / epilogue) ----------------

__global__ void ln_stats_kernel(const float* __restrict__ x, float2* __restrict__ stats, int D) {
    int r = blockIdx.x;
    const float* row = x + (size_t)r * D;
    float s = 0.f, ss = 0.f;
    for (int i = threadIdx.x; i < D; i += blockDim.x) { float v = row[i]; s += v; ss = fmaf(v, v, ss); }
    for (int o = 16; o; o >>= 1) { s += __shfl_xor_sync(0xffffffffu, s, o); ss += __shfl_xor_sync(0xffffffffu, ss, o); }
    __shared__ float as[4], ass[4];
    int w = threadIdx.x >> 5, l = threadIdx.x & 31;
    if (l == 0) { as[w] = s; ass[w] = ss; }
    __syncthreads();
    if (threadIdx.x == 0) {
        s = as[0] + as[1] + as[2] + as[3];
        ss = ass[0] + ass[1] + ass[2] + ass[3];
        float mu = s / D;
        float var = ss / D - mu * mu;
        stats[r] = make_float2(mu, rsqrtf(var + 1e-5f));
    }
}

__global__ void ln_full_kernel(const float* __restrict__ x, const float* __restrict__ g,
                               const float* __restrict__ bt, float* __restrict__ out, int D) {
    int r = blockIdx.x;
    const float* row = x + (size_t)r * D;
    float s = 0.f, ss = 0.f;
    for (int i = threadIdx.x; i < D; i += blockDim.x) { float v = row[i]; s += v; ss = fmaf(v, v, ss); }
    for (int o = 16; o; o >>= 1) { s += __shfl_xor_sync(0xffffffffu, s, o); ss += __shfl_xor_sync(0xffffffffu, ss, o); }
    __shared__ float as[4], ass[4];
    __shared__ float smu, srs;
    int w = threadIdx.x >> 5, l = threadIdx.x & 31;
    if (l == 0) { as[w] = s; ass[w] = ss; }
    __syncthreads();
    if (threadIdx.x == 0) {
        s = as[0] + as[1] + as[2] + as[3];
        ss = ass[0] + ass[1] + ass[2] + ass[3];
        float mu = s / D;
        float var = ss / D - mu * mu;
        smu = mu; srs = rsqrtf(var + 1e-5f);
    }
    __syncthreads();
    float mu = smu, rs = srs;
    for (int i = threadIdx.x; i < D; i += blockDim.x)
        out[(size_t)r * D + i] = (row[i] - mu) * rs * g[i] + bt[i];
}

__global__ void l2n_kernel(float* __restrict__ x, int nseg) {
    int w = (blockIdx.x * blockDim.x + threadIdx.x) >> 5;
    int lane = threadIdx.x & 31;
    if (w >= nseg) return;
    float* seg = x + ((size_t)w << 6);
    float a = seg[lane], c = seg[lane + 32];
    float ss = a * a + c * c;
    for (int o = 16; o; o >>= 1) ss += __shfl_xor_sync(0xffffffffu, ss, o);
    float inv = 1.f / fmaxf(sqrtf(ss), 1e-12f);
    seg[lane] = a * inv;
    seg[lane + 32] = c * inv;
}

__global__ void build_wkvae_kernel(const float* __restrict__ Wk, const float* __restrict__ Wv,
                                   const float* __restrict__ Wa, const float* __restrict__ We,
                                   float* __restrict__ W) {
    int idx = blockIdx.x * blockDim.x + threadIdx.x;
    const int total = ND * NMOx;
    for (; idx < total; idx += gridDim.x * blockDim.x) {
        int r = idx / NMOx, c = idx % NMOx;
        float v;
        if (c < 512)        v = Wk[r * 512 + c];
        else if (c < 1024)  v = Wv[r * 512 + (c - 512)];
        else if (c < 1032)  v = Wa[r * 8 + (c - 1024)];
        else                v = We[r * 8 + (c - 1032)];
        W[idx] = v;
    }
}

__device__ __forceinline__ float dot16(const float4& s0, const float4& s1,
                                       const float4& s2, const float4& s3,
                                       const float* __restrict__ w) {
    float d = s0.x * w[0] + s0.y * w[1] + s0.z * w[2] + s0.w * w[3];
    d += s1.x * w[4] + s1.y * w[5] + s1.z * w[6] + s1.w * w[7];
    d += s2.x * w[8] + s2.y * w[9] + s2.z * w[10] + s2.w * w[11];
    d += s3.x * w[12] + s3.y * w[13] + s3.z * w[14] + s3.w * w[15];
    return d;
}

// initial read: mctx = S_init * q_0
__global__ void read_kernel(const float* __restrict__ state, const float* __restrict__ qbase,
                            long qstride, float* __restrict__ mctx) {
    int bh = blockIdx.x;
    int b = bh >> 3, h = bh & 7;
    __shared__ float sq[64];
    int tid = threadIdx.x;
    if (tid < 64) sq[tid] = qbase[(size_t)b * qstride + h * 64 + tid];
    __syncthreads();
    int row = tid >> 2, qd = tid & 3;
    const float* srow = state + ((size_t)bh << 12) + (row << 6) + (qd << 4);
    float4 s0 = *(const float4*)(srow + 0);
    float4 s1 = *(const float4*)(srow + 4);
    float4 s2 = *(const float4*)(srow + 8);
    float4 s3 = *(const float4*)(srow + 12);
    const float* qq = sq + (qd << 4);
    float d = dot16(s0, s1, s2, s3, qq);
    d += __shfl_xor_sync(0xffffffffu, d, 1);
    d += __shfl_xor_sync(0xffffffffu, d, 2);
    if (qd == 0) mctx[(size_t)b * ND + h * 64 + row] = d;
}

// ---------------- standalone tf32 GEMM (preamble / epilogue) ----------------
struct GemmP {
    const float*  A;   long lda;
    const float*  Bm;  long ldb;
    float*        C;   long ldc;
    int M, N, K;
    int amode;                       // 0 raw, 1 LN, 2 LN+relu
    const float2* stats; long sstride;
    const float*  lng; const float* lnb;
    const float*  bias;
    int epimode;                     // 0 none, 1 relu, 2 add addm
    const float*  addm; long ldadd;
};

__device__ __forceinline__ float tf32r(float x) {
    uint32_t u;
    asm("cvt.rna.tf32.f32 %0, %1;" : "=r"(u) : "f"(x));
    return __uint_as_float(u);
}

__device__ __forceinline__ void mma_tf32(float* c, const uint32_t* a, const uint32_t* b) {
    asm volatile(
        "mma.sync.aligned.m16n8k8.row.col.f32.tf32.tf32.f32 "
        "{%0,%1,%2,%3},{%4,%5,%6,%7},{%8,%9},{%0,%1,%2,%3};"
        : "+f"(c[0]), "+f"(c[1]), "+f"(c[2]), "+f"(c[3])
        : "r"(a[0]), "r"(a[1]), "r"(a[2]), "r"(a[3]), "r"(b[0]), "r"(b[1]));
}

__device__ __forceinline__ float gemm_a_elem(const GemmP& p, int r, int kk) {
    float v = p.A[(size_t)r * p.lda + kk];
    if (p.amode) {
        float2 s = p.stats[(size_t)r * p.sstride];
        v = (v - s.x) * s.y * p.lng[kk] + p.lnb[kk];
        if (p.amode == 2) v = fmaxf(v, 0.f);
    }
    return v;
}

__global__ void gemm_tf32_kernel(GemmP p) {
    __shared__ float As[32 * 65];
    __shared__ float Bs[32 * 65];
    int tid = threadIdx.x;
    int warp = tid >> 5, lane = tid & 31;
    int g = lane >> 2, tig = lane & 3;
    int wm = (warp >> 1) * 32;
    int wn = (warp & 1) * 32;
    int row0 = blockIdx.y * 64;
    int n0 = blockIdx.x * 64;

    float acc[2][4][4];
#pragma unroll
    for (int mt = 0; mt < 2; mt++)
#pragma unroll
        for (int nt = 0; nt < 4; nt++)
#pragma unroll
            for (int e = 0; e < 4; e++) acc[mt][nt][e] = 0.f;

    int nkt = p.K >> 5;
    for (int kt = 0; kt < nkt; kt++) {
        int k0 = kt << 5;
#pragma unroll
        for (int i = 0; i < 16; i++) {
            int idx = i * 128 + tid;
            int m = idx >> 5, k = idx & 31;
            As[k * 65 + m] = tf32r(gemm_a_elem(p, row0 + m, k0 + k));
        }
#pragma unroll
        for (int i = 0; i < 16; i++) {
            int idx = i * 128 + tid;
            int k = idx >> 6, n = idx & 63;
            int col = n0 + n;
            float v = (col < p.N) ? p.Bm[(size_t)(k0 + k) * p.ldb + col] : 0.f;
            Bs[k * 65 + n] = tf32r(v);
        }
        __syncthreads();
#pragma unroll
        for (int ks = 0; ks < 4; ks++) {
            int k8 = ks * 8;
            uint32_t a[2][4], b[4][2];
#pragma unroll
            for (int mt = 0; mt < 2; mt++) {
                int mb = wm + mt * 16 + g;
                a[mt][0] = __float_as_uint(As[(k8 + tig) * 65 + mb]);
                a[mt][1] = __float_as_uint(As[(k8 + tig) * 65 + mb + 8]);
                a[mt][2] = __float_as_uint(As[(k8 + tig + 4) * 65 + mb]);
                a[mt][3] = __float_as_uint(As[(k8 + tig + 4) * 65 + mb + 8]);
            }
#pragma unroll
            for (int nt = 0; nt < 4; nt++) {
                int nb = wn + nt * 8 + g;
                b[nt][0] = __float_as_uint(Bs[(k8 + tig) * 65 + nb]);
                b[nt][1] = __float_as_uint(Bs[(k8 + tig + 4) * 65 + nb]);
            }
#pragma unroll
            for (int mt = 0; mt < 2; mt++)
#pragma unroll
                for (int nt = 0; nt < 4; nt++)
                    mma_tf32(acc[mt][nt], a[mt], b[nt]);
        }
        __syncthreads();
    }

#pragma unroll
    for (int mt = 0; mt < 2; mt++) {
#pragma unroll
        for (int nt = 0; nt < 4; nt++) {
#pragma unroll
            for (int e = 0; e < 4; e++) {
                int r = row0 + wm + mt * 16 + g + ((e >= 2) ? 8 : 0);
                int c = n0 + wn + nt * 8 + tig * 2 + (e & 1);
                if (c < p.N) {
                    float v = acc[mt][nt][e];
                    if (p.bias) v += p.bias[c];
                    if (p.epimode == 1) v = fmaxf(v, 0.f);
                    else if (p.epimode == 2) v += p.addm[(size_t)r * p.ldadd + c];
                    p.C[(size_t)r * p.ldc + c] = v;
                }
            }
        }
    }
}

// ---------------- persistent recurrence kernel ----------------

struct RecP {
    const float* item;
    const float2* istats;
    const float* usnorm;
    float* mctx;
    const float* Q;
    const float* qlast;
    float* y1a; float* y1b; float* y1;
    float2* hstats;
    float* mo; float* modv; float* z;
    float* state;
    const float* mcW1; const float* mcb1;
    const float* mcg; const float* mcbt;
    const float* mcW2; const float* mcb2;
    const float* wkvae;
    const float* ba; const float* be;
    const float* n1g; const float* n1b;
};

__device__ __forceinline__ void grid_sync_dev() {
    __syncthreads();
    if (threadIdx.x == 0) {
        unsigned gen = *((volatile unsigned*)&g_bar_gen);
        __threadfence();
        if (atomicAdd(&g_bar_count, 1) == NBLK - 1) {
            g_bar_count = 0;
            __threadfence();
            atomicAdd(&g_bar_gen, 1);
        } else {
            while (*((volatile unsigned*)&g_bar_gen) == gen) { __nanosleep(64); }
        }
        __threadfence();
    }
    __syncthreads();
}

__device__ __forceinline__ void wg_sync(int wg) {
    asm volatile("bar.sync %0, 128;" :: "r"(wg + 1) : "memory");
}

// warpgroup (128 thr) 32x64 output tile GEMM, K multiple of 32
// amode: 0 raw, 1 LN, 2 LN+relu (stats indexed by global row)
__device__ void wg_gemm(int wg, int wgtid, float* As, float* Bs,
                        const float* __restrict__ A, long lda, int amode,
                        const float2* __restrict__ stats,
                        const float* __restrict__ lng, const float* __restrict__ lnb,
                        const float* __restrict__ B, long ldb, int Ncols,
                        float* __restrict__ C, long ldc, const float* __restrict__ bias,
                        int row0, int n0, int K) {
    int warp = wgtid >> 5, lane = wgtid & 31;
    int gq = lane >> 2, tig = lane & 3;
    int wm = (warp >> 1) * 16;
    int wn = (warp & 1) * 32;
    float acc[4][4];
#pragma unroll
    for (int nt = 0; nt < 4; nt++)
#pragma unroll
        for (int e = 0; e < 4; e++) acc[nt][e] = 0.f;

    int nkt = K >> 5;
    for (int kt = 0; kt < nkt; kt++) {
        int k0 = kt << 5;
#pragma unroll
        for (int i = 0; i < 8; i++) {            // A: 32x32
            int idx = i * 128 + wgtid;
            int m = idx >> 5, k = idx & 31;
            float v = A[(size_t)(row0 + m) * lda + (k0 + k)];
            if (amode) {
                float2 s = stats[row0 + m];
                v = (v - s.x) * s.y * lng[k0 + k] + lnb[k0 + k];
                if (amode == 2) v = fmaxf(v, 0.f);
            }
            As[k * 33 + m] = tf32r(v);
        }
#pragma unroll
        for (int i = 0; i < 16; i++) {           // B: 32x64
            int idx = i * 128 + wgtid;
            int k = idx >> 6, n = idx & 63;
            int col = n0 + n;
            float v = (col < Ncols) ? B[(size_t)(k0 + k) * ldb + col] : 0.f;
            Bs[k * 65 + n] = tf32r(v);
        }
        wg_sync(wg);
#pragma unroll
        for (int ks = 0; ks < 4; ks++) {
            int k8 = ks * 8;
            uint32_t a[4], b[4][2];
            int mb = wm + gq;
            a[0] = __float_as_uint(As[(k8 + tig) * 33 + mb]);
            a[1] = __float_as_uint(As[(k8 + tig) * 33 + mb + 8]);
            a[2] = __float_as_uint(As[(k8 + tig + 4) * 33 + mb]);
            a[3] = __float_as_uint(As[(k8 + tig + 4) * 33 + mb + 8]);
#pragma unroll
            for (int nt = 0; nt < 4; nt++) {
                int nb = wn + nt * 8 + gq;
                b[nt][0] = __float_as_uint(Bs[(k8 + tig) * 65 + nb]);
                b[nt][1] = __float_as_uint(Bs[(k8 + tig + 4) * 65 + nb]);
            }
#pragma unroll
            for (int nt = 0; nt < 4; nt++)
                mma_tf32(acc[nt], a, b[nt]);
        }
        wg_sync(wg);
    }
#pragma unroll
    for (int nt = 0; nt < 4; nt++) {
#pragma unroll
        for (int e = 0; e < 4; e++) {
            int r = row0 + wm + gq + ((e >= 2) ? 8 : 0);
            int c = n0 + wn + nt * 8 + tig * 2 + (e & 1);
            if (c < Ncols) {
                float v = acc[nt][e];
                if (bias) v += bias[c];
                C[(size_t)r * ldc + c] = v;
            }
        }
    }
}

// fused state update + next-step read for one (b,h) pair, by one warpgroup
__device__ void wg_update_pair(int wg, int wgtid, float* scratch, int bh, const RecP& P,
                               const float* __restrict__ qn, long qstride) {
    int b = bh >> 3, h = bh & 7;
    float* sk = scratch;
    float* sv = scratch + 64;
    float* sq = scratch + 128;
    float* sred = scratch + 192;
    const float* zrow = P.z + (size_t)b * NMOx;
    if (wgtid < 64) {
        sk[wgtid] = zrow[h * 64 + wgtid];
        sv[wgtid] = zrow[512 + h * 64 + wgtid];
        sq[wgtid] = qn[(size_t)b * qstride + h * 64 + wgtid];
    }
    wg_sync(wg);
    if (wgtid < 32) {
        float a = sk[wgtid], c = sk[wgtid + 32];
        float ss = a * a + c * c;
        for (int o = 16; o; o >>= 1) ss += __shfl_xor_sync(0xffffffffu, ss, o);
        if (wgtid == 0) sred[0] = fmaxf(sqrtf(ss), 1e-12f);
    }
    wg_sync(wg);
    float inv = 1.f / sred[0];
    const float* morow = P.mo + (size_t)b * NMOx;
    float araw = zrow[1024 + h] + P.ba[h] + morow[1024 + h];
    float eraw = zrow[1032 + h] + P.be[h] + morow[1032 + h];
    float alpha = 1.f / (1.f + expf(-araw));
    float eta = (1.f / (1.f + expf(-eraw))) * SCALE_ETA;
    float om = 1.f - alpha;

    int row = wgtid >> 1, half = wgtid & 1;
    float* srow = P.state + ((size_t)bh << 12) + (row << 6) + half * 32;
    float4 s[8];
#pragma unroll
    for (int i = 0; i < 8; i++) s[i] = *(float4*)(srow + i * 4);

    const float* kh = sk + half * 32;
    const float* qh = sq + half * 32;
    float pred = 0.f;
#pragma unroll
    for (int i = 0; i < 8; i++) {
        pred += s[i].x * kh[i*4] + s[i].y * kh[i*4+1] + s[i].z * kh[i*4+2] + s[i].w * kh[i*4+3];
    }
    pred += __shfl_xor_sync(0xffffffffu, pred, 1);
    pred *= inv;

    float coef = eta * (sv[row] - pred) * inv;
#pragma unroll
    for (int i = 0; i < 8; i++) {
        s[i].x = fmaf(coef, kh[i*4],   om * s[i].x);
        s[i].y = fmaf(coef, kh[i*4+1], om * s[i].y);
        s[i].z = fmaf(coef, kh[i*4+2], om * s[i].z);
        s[i].w = fmaf(coef, kh[i*4+3], om * s[i].w);
        *(float4*)(srow + i * 4) = s[i];
    }
    float qdot = 0.f;
#pragma unroll
    for (int i = 0; i < 8; i++) {
        qdot += s[i].x * qh[i*4] + s[i].y * qh[i*4+1] + s[i].z * qh[i*4+2] + s[i].w * qh[i*4+3];
    }
    qdot += __shfl_xor_sync(0xffffffffu, qdot, 1);
    if (half == 0) P.mctx[(size_t)b * ND + h * 64 + row] = qdot;

    // RACE FIX (Round 5): all warps must finish reading sk/sv/sq/sred before the
    // next loop iteration's writers (warps 0-1) overwrite the scratch buffers.
    wg_sync(wg);
}

__global__ void __launch_bounds__(NTHR, 1) recurrence_kernel(RecP P) {
    extern __shared__ float sm[];
    int tid = threadIdx.x;
    int wg = tid >> 7, wgtid = tid & 127;
    float* As = sm + wg * WG_SMEM_FLOATS;
    float* Bs = As + 32 * 33;
    int wgg = blockIdx.x + NBLK * wg;   // spread mapping: busy wgs land on distinct SMs first

    for (int t = 0; t < NT; t++) {
        // P1: y1 partials. 128 tiles (16 rowblk x 8 colblk) x split2 at concat boundary
        for (int it = wgg; it < 256; it += NWG) {
            int s = it & 1, tile = it >> 1;
            int row0 = (tile >> 3) * 32, n0 = (tile & 7) * 64;
            if (s == 0)
                wg_gemm(wg, wgtid, As, Bs, P.usnorm, ND, 0, nullptr, nullptr, nullptr,
                        P.mcW1, ND, ND, P.y1a, ND, nullptr, row0, n0, ND);
            else
                wg_gemm(wg, wgtid, As, Bs, P.mctx, ND, 0, nullptr, nullptr, nullptr,
                        P.mcW1 + (size_t)512 * ND, ND, ND, P.y1b, ND, nullptr, row0, n0, ND);
        }
        grid_sync_dev();

        // P2: y1 = p0 + p1 + bias, LN stats per row (one warp per row)
        {
            int warpid = tid >> 5, lane = tid & 31;
            for (int r = blockIdx.x + NBLK * warpid; r < NB; r += NBLK * 16) {
                const float* pa = P.y1a + (size_t)r * ND;
                const float* pb = P.y1b + (size_t)r * ND;
                float* py = P.y1 + (size_t)r * ND;
                float s = 0.f, ss = 0.f;
                for (int c = lane; c < ND; c += 32) {
                    float v = pa[c] + pb[c] + P.mcb1[c];
                    py[c] = v;
                    s += v; ss = fmaf(v, v, ss);
                }
                for (int o = 16; o; o >>= 1) {
                    s += __shfl_xor_sync(0xffffffffu, s, o);
                    ss += __shfl_xor_sync(0xffffffffu, ss, o);
                }
                if (lane == 0) {
                    float mu = s / ND;
                    float var = ss / ND - mu * mu;
                    P.hstats[r] = make_float2(mu, rsqrtf(var + 1e-5f));
                }
            }
        }
        grid_sync_dev();

        // P3: mo = relu(LN(y1)) @ mcW2 + mcb2.  16 x 17 = 272 tiles
        for (int it = wgg; it < 272; it += NWG) {
            int row0 = (it / 17) * 32, n0 = (it % 17) * 64;
            wg_gemm(wg, wgtid, As, Bs, P.y1, ND, 2, P.hstats, P.mcg, P.mcbt,
                    P.mcW2, NMOx, NMOx, P.mo, NMOx, P.mcb2, row0, n0, ND);
        }
        grid_sync_dev();

        // P4: mod = i_norm * (1 + tanh(gamma)) + beta
        {
            const float* item_t = P.item + (size_t)t * ND;
            for (int idx = blockIdx.x * NTHR + tid; idx < NB * ND; idx += NBLK * NTHR) {
                int b = idx >> 9, d = idx & 511;
                float2 st = P.istats[(size_t)b * NT + t];
                float inorm = (item_t[(size_t)b * NT * ND + d] - st.x) * st.y * P.n1g[d] + P.n1b[d];
                float gm = P.mo[(size_t)b * NMOx + d];
                float bt = P.mo[(size_t)b * NMOx + 512 + d];
                P.modv[idx] = inorm * (1.f + tanhf(gm)) + bt;
            }
        }
        grid_sync_dev();

        // P5: z = mod @ wkvae.  272 tiles
        for (int it = wgg; it < 272; it += NWG) {
            int row0 = (it / 17) * 32, n0 = (it % 17) * 64;
            wg_gemm(wg, wgtid, As, Bs, P.modv, ND, 0, nullptr, nullptr, nullptr,
                    P.wkvae, NMOx, NMOx, P.z, NMOx, nullptr, row0, n0, ND);
        }
        grid_sync_dev();

        // P6: state update + fused read of next context
        {
            const float* qn; long qstride;
            if (t < NT - 1) { qn = P.Q + (size_t)(t + 1) * ND; qstride = (long)NT * ND; }
            else            { qn = P.qlast;                    qstride = (long)ND; }
            for (int pair = wgg; pair < NB * NH; pair += NWG)
                wg_update_pair(wg, wgtid, As, pair, P, qn, qstride);
        }
        grid_sync_dev();
    }
}

// ---------------- host launcher ----------------

static void launch_gemm(const float* A, long lda, const float* Bm, long ldb, float* C, long ldc,
                        int M, int N, int K, int amode,
                        const float2* stats, long sstride, const float* lng, const float* lnb,
                        const float* bias, int epi, const float* addm, long ldadd) {
    GemmP p;
    p.A = A; p.lda = lda; p.Bm = Bm; p.ldb = ldb; p.C = C; p.ldc = ldc;
    p.M = M; p.N = N; p.K = K; p.amode = amode;
    p.stats = stats; p.sstride = sstride; p.lng = lng; p.lnb = lnb;
    p.bias = bias; p.epimode = epi; p.addm = addm; p.ldadd = ldadd;
    dim3 grid((N + 63) / 64, M / 64);
    gemm_tf32_kernel<<<grid, 128>>>(p);
}

extern "C" void kernel_launch(void* const* d_in, const int* in_sizes, int n_in,
                              void* d_out, int out_size) {
    const float* item  = (const float*)d_in[0];
    const float* ustat = (const float*)d_in[1];
    const float* lastI = (const float*)d_in[2];
    const float* init  = (const float*)d_in[3];
    const float* Wq    = (const float*)d_in[4];
    const float* Wk    = (const float*)d_in[5];
    const float* Wv    = (const float*)d_in[6];
    const float* Wa    = (const float*)d_in[7];
    const float* ba    = (const float*)d_in[8];
    const float* We    = (const float*)d_in[9];
    const float* be    = (const float*)d_in[10];
    const float* mcW1  = (const float*)d_in[11];
    const float* mcb1  = (const float*)d_in[12];
    const float* mcg   = (const float*)d_in[13];
    const float* mcbt  = (const float*)d_in[14];
    const float* mcW2  = (const float*)d_in[15];
    const float* mcb2  = (const float*)d_in[16];
    const float* Wo    = (const float*)d_in[17];
    const float* bo    = (const float*)d_in[18];
    const float* W1    = (const float*)d_in[19];
    const float* b1    = (const float*)d_in[20];
    const float* W2    = (const float*)d_in[21];
    const float* b2    = (const float*)d_in[22];
    const float* n1g   = (const float*)d_in[23];
    const float* n1b   = (const float*)d_in[24];
    const float* n2g   = (const float*)d_in[25];
    const float* n2b   = (const float*)d_in[26];
    float* out = (float*)d_out;

    float *state, *usnorm, *Q, *qlast, *mctx, *y1a, *y1b, *y1, *mov, *modv, *z, *wkvae, *x, *a1;
    float2 *istats, *lstats, *hstats, *xstats;
    cudaGetSymbolAddress((void**)&state,  g_state);
    cudaGetSymbolAddress((void**)&istats, g_istats);
    cudaGetSymbolAddress((void**)&lstats, g_lstats);
    cudaGetSymbolAddress((void**)&hstats, g_hstats);
    cudaGetSymbolAddress((void**)&xstats, g_xstats);
    cudaGetSymbolAddress((void**)&usnorm, g_usnorm);
    cudaGetSymbolAddress((void**)&Q,      g_Q);
    cudaGetSymbolAddress((void**)&qlast,  g_qlast);
    cudaGetSymbolAddress((void**)&mctx,   g_mctx);
    cudaGetSymbolAddress((void**)&y1a,    g_y1a);
    cudaGetSymbolAddress((void**)&y1b,    g_y1b);
    cudaGetSymbolAddress((void**)&y1,     g_y1);
    cudaGetSymbolAddress((void**)&mov,    g_mo);
    cudaGetSymbolAddress((void**)&modv,   g_mod);
    cudaGetSymbolAddress((void**)&z,      g_z);
    cudaGetSymbolAddress((void**)&wkvae,  g_wkvae);
    cudaGetSymbolAddress((void**)&x,      g_x);
    cudaGetSymbolAddress((void**)&a1,     g_a1);

    cudaFuncSetAttribute(recurrence_kernel, cudaFuncAttributeMaxDynamicSharedMemorySize, SMEM_BYTES);

    // ---- preamble ----
    cudaMemcpyAsync(state, init, (size_t)NB * NH * NDH * NDH * sizeof(float),
                    cudaMemcpyDeviceToDevice);
    ln_stats_kernel<<<NB * NT, 128>>>(item, istats, ND);
    ln_full_kernel<<<NB, 128>>>(ustat, n1g, n1b, usnorm, ND);
    ln_stats_kernel<<<NB, 128>>>(lastI, lstats, ND);
    build_wkvae_kernel<<<2080, 256>>>(Wk, Wv, Wa, We, wkvae);

    launch_gemm(item, ND, Wq, ND, Q, ND, NB * NT, ND, ND, 1,
                istats, 1, n1g, n1b, nullptr, 0, nullptr, 0);
    launch_gemm(lastI, ND, Wq, ND, qlast, ND, NB, ND, ND, 1,
                lstats, 1, n1g, n1b, nullptr, 0, nullptr, 0);
    l2n_kernel<<<(NB * NT * NH) / 8, 256>>>(Q, NB * NT * NH);
    l2n_kernel<<<(NB * NH) / 8, 256>>>(qlast, NB * NH);

    read_kernel<<<NB * NH, 256>>>(state, Q, (long)NT * ND, mctx);

    // ---- full recurrence in ONE persistent kernel ----
    RecP P;
    P.item = item; P.istats = istats; P.usnorm = usnorm; P.mctx = mctx;
    P.Q = Q; P.qlast = qlast;
    P.y1a = y1a; P.y1b = y1b; P.y1 = y1; P.hstats = hstats;
    P.mo = mov; P.modv = modv; P.z = z; P.state = state;
    P.mcW1 = mcW1; P.mcb1 = mcb1; P.mcg = mcg; P.mcbt = mcbt;
    P.mcW2 = mcW2; P.mcb2 = mcb2; P.wkvae = wkvae;
    P.ba = ba; P.be = be; P.n1g = n1g; P.n1b = n1b;
    recurrence_kernel<<<NBLK, NTHR, SMEM_BYTES>>>(P);

    // ---- readout + FFN ----
    launch_gemm(mctx, ND, Wo, ND, x, ND, NB, ND, ND, 0,
                nullptr, 0, nullptr, nullptr, bo, 2, ustat, ND);
    ln_stats_kernel<<<NB, 128>>>(x, xstats, ND);
    launch_gemm(x, ND, W1, NFF, a1, NFF, NB, NFF, ND, 1,
                xstats, 1, n2g, n2b, b1, 1, nullptr, 0);
    launch_gemm(a1, NFF, W2, ND, out, ND, NB, ND, NFF, 0,
                nullptr, 0, nullptr, nullptr, b2, 2, x, ND);
}

// round 6
// speedup vs baseline: 1.7662x; 1.0277x over previous
#include <cuda_runtime.h>
#include <math.h>
#include <stdint.h>

// ---------------- problem constants ----------------
#define NB   512
#define NT   64
#define ND   512
#define NH   8
#define NDH  64
#define NFF  2048
#define NMOx 1040
#define SCALE_ETA 0.125f
#define NBLK 148
#define NTHR 512
#define NWG  (NBLK * 4)   // 592 warpgroup workers

#define WG_SMEM_FLOATS (32 * 33 + 32 * 65)   // 3136
#define SMEM_BYTES (4 * WG_SMEM_FLOATS * 4)  // 50176

// ---------------- device scratch ----------------
__device__ float  g_state[NB*NH*NDH*NDH];
__device__ float2 g_istats[NB*NT];
__device__ float2 g_lstats[NB];
__device__ float2 g_hstats[NB];
__device__ float2 g_xstats[NB];
__device__ float  g_usnorm[NB*ND];
__device__ float  g_Q[(NB*NT + NB)*ND];      // Q rows then qlast rows
__device__ float  g_mctx[NB*ND];
__device__ float  g_y1p[4*NB*ND];            // 4 K-split partials of y1
__device__ float  g_y1[NB*ND];
__device__ float  g_moa[NB*NMOx];
__device__ float  g_mob[NB*NMOx];
__device__ float  g_ae[NB*16];               // reduced alpha/eta bias cols (1024..1039)
__device__ float  g_mod[NB*ND];
__device__ float  g_za[NB*NMOx];
__device__ float  g_zb[NB*NMOx];
__device__ float  g_wkvae[ND*NMOx];
__device__ float  g_x[NB*ND];
__device__ float  g_a1[NB*NFF];
__device__ unsigned g_bar_count = 0;
__device__ unsigned g_bar_gen   = 0;

// ---------------- preamble / epilogue helper kernels ----------------

// combined: rows [0, NB*NT) = item rows -> istats; rows [NB*NT, +NB) = lastI -> lstats
__global__ void ln_stats_all_kernel(const float* __restrict__ item, const float* __restrict__ lastI,
                                    float2* __restrict__ istats, float2* __restrict__ lstats) {
    int r = blockIdx.x;
    const float* row;
    float2* dst;
    if (r < NB * NT) { row = item + (size_t)r * ND; dst = istats + r; }
    else             { row = lastI + (size_t)(r - NB * NT) * ND; dst = lstats + (r - NB * NT); }
    float s = 0.f, ss = 0.f;
    for (int i = threadIdx.x; i < ND; i += blockDim.x) { float v = row[i]; s += v; ss = fmaf(v, v, ss); }
    for (int o = 16; o; o >>= 1) { s += __shfl_xor_sync(0xffffffffu, s, o); ss += __shfl_xor_sync(0xffffffffu, ss, o); }
    __shared__ float as[4], ass[4];
    int w = threadIdx.x >> 5, l = threadIdx.x & 31;
    if (l == 0) { as[w] = s; ass[w] = ss; }
    __syncthreads();
    if (threadIdx.x == 0) {
        s = as[0] + as[1] + as[2] + as[3];
        ss = ass[0] + ass[1] + ass[2] + ass[3];
        float mu = s / ND;
        float var = ss / ND - mu * mu;
        *dst = make_float2(mu, rsqrtf(var + 1e-5f));
    }
}

__global__ void ln_stats_kernel(const float* __restrict__ x, float2* __restrict__ stats, int D) {
    int r = blockIdx.x;
    const float* row = x + (size_t)r * D;
    float s = 0.f, ss = 0.f;
    for (int i = threadIdx.x; i < D; i += blockDim.x) { float v = row[i]; s += v; ss = fmaf(v, v, ss); }
    for (int o = 16; o; o >>= 1) { s += __shfl_xor_sync(0xffffffffu, s, o); ss += __shfl_xor_sync(0xffffffffu, ss, o); }
    __shared__ float as[4], ass[4];
    int w = threadIdx.x >> 5, l = threadIdx.x & 31;
    if (l == 0) { as[w] = s; ass[w] = ss; }
    __syncthreads();
    if (threadIdx.x == 0) {
        s = as[0] + as[1] + as[2] + as[3];
        ss = ass[0] + ass[1] + ass[2] + ass[3];
        float mu = s / D;
        float var = ss / D - mu * mu;
        stats[r] = make_float2(mu, rsqrtf(var + 1e-5f));
    }
}

__global__ void ln_full_kernel(const float* __restrict__ x, const float* __restrict__ g,
                               const float* __restrict__ bt, float* __restrict__ out, int D) {
    int r = blockIdx.x;
    const float* row = x + (size_t)r * D;
    float s = 0.f, ss = 0.f;
    for (int i = threadIdx.x; i < D; i += blockDim.x) { float v = row[i]; s += v; ss = fmaf(v, v, ss); }
    for (int o = 16; o; o >>= 1) { s += __shfl_xor_sync(0xffffffffu, s, o); ss += __shfl_xor_sync(0xffffffffu, ss, o); }
    __shared__ float as[4], ass[4];
    __shared__ float smu, srs;
    int w = threadIdx.x >> 5, l = threadIdx.x & 31;
    if (l == 0) { as[w] = s; ass[w] = ss; }
    __syncthreads();
    if (threadIdx.x == 0) {
        s = as[0] + as[1] + as[2] + as[3];
        ss = ass[0] + ass[1] + ass[2] + ass[3];
        float mu = s / D;
        float var = ss / D - mu * mu;
        smu = mu; srs = rsqrtf(var + 1e-5f);
    }
    __syncthreads();
    float mu = smu, rs = srs;
    for (int i = threadIdx.x; i < D; i += blockDim.x)
        out[(size_t)r * D + i] = (row[i] - mu) * rs * g[i] + bt[i];
}

__global__ void l2n_kernel(float* __restrict__ x, int nseg) {
    int w = (blockIdx.x * blockDim.x + threadIdx.x) >> 5;
    int lane = threadIdx.x & 31;
    if (w >= nseg) return;
    float* seg = x + ((size_t)w << 6);
    float a = seg[lane], c = seg[lane + 32];
    float ss = a * a + c * c;
    for (int o = 16; o; o >>= 1) ss += __shfl_xor_sync(0xffffffffu, ss, o);
    float inv = 1.f / fmaxf(sqrtf(ss), 1e-12f);
    seg[lane] = a * inv;
    seg[lane + 32] = c * inv;
}

__global__ void build_wkvae_kernel(const float* __restrict__ Wk, const float* __restrict__ Wv,
                                   const float* __restrict__ Wa, const float* __restrict__ We,
                                   float* __restrict__ W) {
    int idx = blockIdx.x * blockDim.x + threadIdx.x;
    const int total = ND * NMOx;
    for (; idx < total; idx += gridDim.x * blockDim.x) {
        int r = idx / NMOx, c = idx % NMOx;
        float v;
        if (c < 512)        v = Wk[r * 512 + c];
        else if (c < 1024)  v = Wv[r * 512 + (c - 512)];
        else if (c < 1032)  v = Wa[r * 8 + (c - 1024)];
        else                v = We[r * 8 + (c - 1032)];
        W[idx] = v;
    }
}

// ---------------- standalone tf32 GEMM ----------------
// amode: 0 raw, 1 LN, 2 LN+relu, 3 dual-source LN (A rows < NB*NT from A/stats, else A2/stats2)
struct GemmP {
    const float*  A;   long lda;
    const float*  A2;
    const float*  Bm;  long ldb;
    float*        C;   long ldc;
    int M, N, K;
    int amode;
    const float2* stats;
    const float2* stats2;
    const float*  lng; const float* lnb;
    const float*  bias;
    int epimode;                     // 0 none, 1 relu, 2 add addm
    const float*  addm; long ldadd;
};

__device__ __forceinline__ float tf32r(float x) {
    uint32_t u;
    asm("cvt.rna.tf32.f32 %0, %1;" : "=r"(u) : "f"(x));
    return __uint_as_float(u);
}

__device__ __forceinline__ void mma_tf32(float* c, const uint32_t* a, const uint32_t* b) {
    asm volatile(
        "mma.sync.aligned.m16n8k8.row.col.f32.tf32.tf32.f32 "
        "{%0,%1,%2,%3},{%4,%5,%6,%7},{%8,%9},{%0,%1,%2,%3};"
        : "+f"(c[0]), "+f"(c[1]), "+f"(c[2]), "+f"(c[3])
        : "r"(a[0]), "r"(a[1]), "r"(a[2]), "r"(a[3]), "r"(b[0]), "r"(b[1]));
}

__device__ __forceinline__ float gemm_a_elem(const GemmP& p, int r, int kk) {
    if (p.amode == 3) {
        float v; float2 s;
        if (r < NB * NT) { v = p.A[(size_t)r * p.lda + kk]; s = p.stats[r]; }
        else             { v = p.A2[(size_t)(r - NB * NT) * p.lda + kk]; s = p.stats2[r - NB * NT]; }
        return (v - s.x) * s.y * p.lng[kk] + p.lnb[kk];
    }
    float v = p.A[(size_t)r * p.lda + kk];
    if (p.amode) {
        float2 s = p.stats[r];
        v = (v - s.x) * s.y * p.lng[kk] + p.lnb[kk];
        if (p.amode == 2) v = fmaxf(v, 0.f);
    }
    return v;
}

__global__ void gemm_tf32_kernel(GemmP p) {
    __shared__ float As[32 * 65];
    __shared__ float Bs[32 * 65];
    int tid = threadIdx.x;
    int warp = tid >> 5, lane = tid & 31;
    int g = lane >> 2, tig = lane & 3;
    int wm = (warp >> 1) * 32;
    int wn = (warp & 1) * 32;
    int row0 = blockIdx.y * 64;
    int n0 = blockIdx.x * 64;

    float acc[2][4][4];
#pragma unroll
    for (int mt = 0; mt < 2; mt++)
#pragma unroll
        for (int nt = 0; nt < 4; nt++)
#pragma unroll
            for (int e = 0; e < 4; e++) acc[mt][nt][e] = 0.f;

    int nkt = p.K >> 5;
    for (int kt = 0; kt < nkt; kt++) {
        int k0 = kt << 5;
#pragma unroll
        for (int i = 0; i < 16; i++) {
            int idx = i * 128 + tid;
            int m = idx >> 5, k = idx & 31;
            As[k * 65 + m] = tf32r(gemm_a_elem(p, row0 + m, k0 + k));
        }
#pragma unroll
        for (int i = 0; i < 16; i++) {
            int idx = i * 128 + tid;
            int k = idx >> 6, n = idx & 63;
            int col = n0 + n;
            float v = (col < p.N) ? p.Bm[(size_t)(k0 + k) * p.ldb + col] : 0.f;
            Bs[k * 65 + n] = tf32r(v);
        }
        __syncthreads();
#pragma unroll
        for (int ks = 0; ks < 4; ks++) {
            int k8 = ks * 8;
            uint32_t a[2][4], b[4][2];
#pragma unroll
            for (int mt = 0; mt < 2; mt++) {
                int mb = wm + mt * 16 + g;
                a[mt][0] = __float_as_uint(As[(k8 + tig) * 65 + mb]);
                a[mt][1] = __float_as_uint(As[(k8 + tig) * 65 + mb + 8]);
                a[mt][2] = __float_as_uint(As[(k8 + tig + 4) * 65 + mb]);
                a[mt][3] = __float_as_uint(As[(k8 + tig + 4) * 65 + mb + 8]);
            }
#pragma unroll
            for (int nt = 0; nt < 4; nt++) {
                int nb = wn + nt * 8 + g;
                b[nt][0] = __float_as_uint(Bs[(k8 + tig) * 65 + nb]);
                b[nt][1] = __float_as_uint(Bs[(k8 + tig + 4) * 65 + nb]);
            }
#pragma unroll
            for (int mt = 0; mt < 2; mt++)
#pragma unroll
                for (int nt = 0; nt < 4; nt++)
                    mma_tf32(acc[mt][nt], a[mt], b[nt]);
        }
        __syncthreads();
    }

#pragma unroll
    for (int mt = 0; mt < 2; mt++) {
#pragma unroll
        for (int nt = 0; nt < 4; nt++) {
#pragma unroll
            for (int e = 0; e < 4; e++) {
                int r = row0 + wm + mt * 16 + g + ((e >= 2) ? 8 : 0);
                int c = n0 + wn + nt * 8 + tig * 2 + (e & 1);
                if (c < p.N) {
                    float v = acc[mt][nt][e];
                    if (p.bias) v += p.bias[c];
                    if (p.epimode == 1) v = fmaxf(v, 0.f);
                    else if (p.epimode == 2) v += p.addm[(size_t)r * p.ldadd + c];
                    p.C[(size_t)r * p.ldc + c] = v;
                }
            }
        }
    }
}

// ---------------- persistent recurrence kernel ----------------

struct RecP {
    const float* item;
    const float2* istats;
    const float* usnorm;
    float* mctx;
    const float* Q;          // qlast rows at offset NB*NT*ND
    const float* init;
    float* y1p; float* y1;
    float2* hstats;
    float* moa; float* mob; float* ae;
    float* modv;
    float* za; float* zb;
    float* state;
    const float* mcW1; const float* mcb1;
    const float* mcg; const float* mcbt;
    const float* mcW2; const float* mcb2;
    const float* wkvae;
    const float* ba; const float* be;
    const float* n1g; const float* n1b;
};

__device__ __forceinline__ void grid_sync_dev() {
    __syncthreads();
    if (threadIdx.x == 0) {
        unsigned gen = *((volatile unsigned*)&g_bar_gen);
        __threadfence();
        if (atomicAdd(&g_bar_count, 1) == NBLK - 1) {
            g_bar_count = 0;
            __threadfence();
            atomicAdd(&g_bar_gen, 1);
        } else {
            while (*((volatile unsigned*)&g_bar_gen) == gen) { __nanosleep(64); }
        }
        __threadfence();
    }
    __syncthreads();
}

__device__ __forceinline__ void wg_sync(int wg) {
    asm volatile("bar.sync %0, 128;" :: "r"(wg + 1) : "memory");
}

// warpgroup (128 thr) 32x64 tile GEMM, K multiple of 32 (pointers pre-offset for K-splits)
// amode: 0 raw, 2 LN+relu
__device__ void wg_gemm(int wg, int wgtid, float* As, float* Bs,
                        const float* __restrict__ A, long lda, int amode,
                        const float2* __restrict__ stats,
                        const float* __restrict__ lng, const float* __restrict__ lnb,
                        const float* __restrict__ B, long ldb, int Ncols,
                        float* __restrict__ C, long ldc,
                        int row0, int n0, int K) {
    int warp = wgtid >> 5, lane = wgtid & 31;
    int gq = lane >> 2, tig = lane & 3;
    int wm = (warp >> 1) * 16;
    int wn = (warp & 1) * 32;
    float acc[4][4];
#pragma unroll
    for (int nt = 0; nt < 4; nt++)
#pragma unroll
        for (int e = 0; e < 4; e++) acc[nt][e] = 0.f;

    int nkt = K >> 5;
    for (int kt = 0; kt < nkt; kt++) {
        int k0 = kt << 5;
#pragma unroll
        for (int i = 0; i < 8; i++) {
            int idx = i * 128 + wgtid;
            int m = idx >> 5, k = idx & 31;
            float v = A[(size_t)(row0 + m) * lda + (k0 + k)];
            if (amode) {
                float2 s = stats[row0 + m];
                v = (v - s.x) * s.y * lng[k0 + k] + lnb[k0 + k];
                if (amode == 2) v = fmaxf(v, 0.f);
            }
            As[k * 33 + m] = tf32r(v);
        }
#pragma unroll
        for (int i = 0; i < 16; i++) {
            int idx = i * 128 + wgtid;
            int k = idx >> 6, n = idx & 63;
            int col = n0 + n;
            float v = (col < Ncols) ? B[(size_t)(k0 + k) * ldb + col] : 0.f;
            Bs[k * 65 + n] = tf32r(v);
        }
        wg_sync(wg);
#pragma unroll
        for (int ks = 0; ks < 4; ks++) {
            int k8 = ks * 8;
            uint32_t a[4], b[4][2];
            int mb = wm + gq;
            a[0] = __float_as_uint(As[(k8 + tig) * 33 + mb]);
            a[1] = __float_as_uint(As[(k8 + tig) * 33 + mb + 8]);
            a[2] = __float_as_uint(As[(k8 + tig + 4) * 33 + mb]);
            a[3] = __float_as_uint(As[(k8 + tig + 4) * 33 + mb + 8]);
#pragma unroll
            for (int nt = 0; nt < 4; nt++) {
                int nb = wn + nt * 8 + gq;
                b[nt][0] = __float_as_uint(Bs[(k8 + tig) * 65 + nb]);
                b[nt][1] = __float_as_uint(Bs[(k8 + tig + 4) * 65 + nb]);
            }
#pragma unroll
            for (int nt = 0; nt < 4; nt++)
                mma_tf32(acc[nt], a, b[nt]);
        }
        wg_sync(wg);
    }
#pragma unroll
    for (int nt = 0; nt < 4; nt++) {
#pragma unroll
        for (int e = 0; e < 4; e++) {
            int r = row0 + wm + gq + ((e >= 2) ? 8 : 0);
            int c = n0 + wn + nt * 8 + tig * 2 + (e & 1);
            if (c < Ncols)
                C[(size_t)r * ldc + c] = acc[nt][e];
        }
    }
}

// P0: copy init->state and compute mctx = init * q0 for one (b,h) pair
__device__ void wg_read_pair(int wg, int wgtid, float* scratch, int bh, const RecP& P) {
    int b = bh >> 3, h = bh & 7;
    float* sq = scratch;
    if (wgtid < 64) sq[wgtid] = P.Q[(size_t)b * NT * ND + h * 64 + wgtid];
    wg_sync(wg);
    int row = wgtid >> 1, half = wgtid & 1;
    const float* irow = P.init + ((size_t)bh << 12) + (row << 6) + half * 32;
    float* srow = P.state + ((size_t)bh << 12) + (row << 6) + half * 32;
    const float* qh = sq + half * 32;
    float4 s[8];
    float qdot = 0.f;
#pragma unroll
    for (int i = 0; i < 8; i++) {
        s[i] = *(const float4*)(irow + i * 4);
        *(float4*)(srow + i * 4) = s[i];
        qdot += s[i].x * qh[i*4] + s[i].y * qh[i*4+1] + s[i].z * qh[i*4+2] + s[i].w * qh[i*4+3];
    }
    qdot += __shfl_xor_sync(0xffffffffu, qdot, 1);
    if (half == 0) P.mctx[(size_t)b * ND + h * 64 + row] = qdot;
    wg_sync(wg);
}

// P6: state update + fused read of next context; z = za + zb on the fly
__device__ void wg_update_pair(int wg, int wgtid, float* scratch, int bh, const RecP& P,
                               const float* __restrict__ qn, long qstride) {
    int b = bh >> 3, h = bh & 7;
    float* sk = scratch;
    float* sv = scratch + 64;
    float* sq = scratch + 128;
    float* sred = scratch + 192;
    const float* zra = P.za + (size_t)b * NMOx;
    const float* zrb = P.zb + (size_t)b * NMOx;
    if (wgtid < 64) {
        sk[wgtid] = zra[h * 64 + wgtid] + zrb[h * 64 + wgtid];
        sv[wgtid] = zra[512 + h * 64 + wgtid] + zrb[512 + h * 64 + wgtid];
        sq[wgtid] = qn[(size_t)b * qstride + h * 64 + wgtid];
    }
    wg_sync(wg);
    if (wgtid < 32) {
        float a = sk[wgtid], c = sk[wgtid + 32];
        float ss = a * a + c * c;
        for (int o = 16; o; o >>= 1) ss += __shfl_xor_sync(0xffffffffu, ss, o);
        if (wgtid == 0) sred[0] = fmaxf(sqrtf(ss), 1e-12f);
    }
    wg_sync(wg);
    float inv = 1.f / sred[0];
    const float* aerow = P.ae + (size_t)b * 16;
    float araw = (zra[1024 + h] + zrb[1024 + h]) + P.ba[h] + aerow[h];
    float eraw = (zra[1032 + h] + zrb[1032 + h]) + P.be[h] + aerow[8 + h];
    float alpha = 1.f / (1.f + expf(-araw));
    float eta = (1.f / (1.f + expf(-eraw))) * SCALE_ETA;
    float om = 1.f - alpha;

    int row = wgtid >> 1, half = wgtid & 1;
    float* srow = P.state + ((size_t)bh << 12) + (row << 6) + half * 32;
    float4 s[8];
#pragma unroll
    for (int i = 0; i < 8; i++) s[i] = *(float4*)(srow + i * 4);

    const float* kh = sk + half * 32;
    const float* qh = sq + half * 32;
    float pred = 0.f;
#pragma unroll
    for (int i = 0; i < 8; i++) {
        pred += s[i].x * kh[i*4] + s[i].y * kh[i*4+1] + s[i].z * kh[i*4+2] + s[i].w * kh[i*4+3];
    }
    pred += __shfl_xor_sync(0xffffffffu, pred, 1);
    pred *= inv;

    float coef = eta * (sv[row] - pred) * inv;
    float qdot = 0.f;
#pragma unroll
    for (int i = 0; i < 8; i++) {
        s[i].x = fmaf(coef, kh[i*4],   om * s[i].x);
        s[i].y = fmaf(coef, kh[i*4+1], om * s[i].y);
        s[i].z = fmaf(coef, kh[i*4+2], om * s[i].z);
        s[i].w = fmaf(coef, kh[i*4+3], om * s[i].w);
        *(float4*)(srow + i * 4) = s[i];
        qdot += s[i].x * qh[i*4] + s[i].y * qh[i*4+1] + s[i].z * qh[i*4+2] + s[i].w * qh[i*4+3];
    }
    qdot += __shfl_xor_sync(0xffffffffu, qdot, 1);
    if (half == 0) P.mctx[(size_t)b * ND + h * 64 + row] = qdot;
    wg_sync(wg);   // protect scratch from next iteration's writers
}

__global__ void __launch_bounds__(NTHR, 1) recurrence_kernel(RecP P) {
    extern __shared__ float sm[];
    int tid = threadIdx.x;
    int wg = tid >> 7, wgtid = tid & 127;
    float* As = sm + wg * WG_SMEM_FLOATS;
    float* Bs = As + 32 * 33;
    int wgg = blockIdx.x + NBLK * wg;

    // P0: state init copy + initial read mctx = init * q0
    for (int pair = wgg; pair < NB * NH; pair += NWG)
        wg_read_pair(wg, wgtid, As, pair, P);
    grid_sync_dev();

    for (int t = 0; t < NT; t++) {
        // P1: y1 partials. 4 partials (source x K-half) x 128 tiles = 512 tiles, K=256 each
        for (int it = wgg; it < 512; it += NWG) {
            int p = it & 3, tile = it >> 2;
            int row0 = (tile >> 3) * 32, n0 = (tile & 7) * 64;
            const float* Asrc = (p < 2) ? P.usnorm : P.mctx;
            int kh = p & 1;
            wg_gemm(wg, wgtid, As, Bs,
                    Asrc + kh * 256, ND, 0, nullptr, nullptr, nullptr,
                    P.mcW1 + (size_t)((p >> 1) * 512 + kh * 256) * ND, ND, ND,
                    P.y1p + (size_t)p * NB * ND, ND, row0, n0, 256);
        }
        grid_sync_dev();

        // P2: y1 = sum of 4 partials + bias, LN stats per row
        {
            int warpid = tid >> 5, lane = tid & 31;
            for (int r = blockIdx.x + NBLK * warpid; r < NB; r += NBLK * 16) {
                const float* p0 = P.y1p + (size_t)r * ND;
                const float* p1 = p0 + (size_t)NB * ND;
                const float* p2 = p1 + (size_t)NB * ND;
                const float* p3 = p2 + (size_t)NB * ND;
                float* py = P.y1 + (size_t)r * ND;
                float s = 0.f, ss = 0.f;
                for (int c = lane; c < ND; c += 32) {
                    float v = p0[c] + p1[c] + p2[c] + p3[c] + P.mcb1[c];
                    py[c] = v;
                    s += v; ss = fmaf(v, v, ss);
                }
                for (int o = 16; o; o >>= 1) {
                    s += __shfl_xor_sync(0xffffffffu, s, o);
                    ss += __shfl_xor_sync(0xffffffffu, ss, o);
                }
                if (lane == 0) {
                    float mu = s / ND;
                    float var = ss / ND - mu * mu;
                    P.hstats[r] = make_float2(mu, rsqrtf(var + 1e-5f));
                }
            }
        }
        grid_sync_dev();

        // P3: mo partials = relu(LN(y1)) @ mcW2, K split 2 -> 544 tiles
        for (int it = wgg; it < 544; it += NWG) {
            int kh = it & 1, tile = it >> 1;
            int row0 = (tile / 17) * 32, n0 = (tile % 17) * 64;
            wg_gemm(wg, wgtid, As, Bs,
                    P.y1 + kh * 256, ND, 2, P.hstats, P.mcg + kh * 256, P.mcbt + kh * 256,
                    P.mcW2 + (size_t)(kh * 256) * NMOx, NMOx, NMOx,
                    kh ? P.mob : P.moa, NMOx, row0, n0, 256);
        }
        grid_sync_dev();

        // P4: mo reduce + mod = i_norm * (1 + tanh(gamma)) + beta ; ae cols
        {
            const float* item_t = P.item + (size_t)t * ND;
            int gid = blockIdx.x * NTHR + tid;
            for (int idx = gid; idx < NB * ND; idx += NBLK * NTHR) {
                int b = idx >> 9, d = idx & 511;
                const float* ma = P.moa + (size_t)b * NMOx;
                const float* mb = P.mob + (size_t)b * NMOx;
                float gm = ma[d] + mb[d] + P.mcb2[d];
                float bt = ma[512 + d] + mb[512 + d] + P.mcb2[512 + d];
                float2 st = P.istats[(size_t)b * NT + t];
                float inorm = (item_t[(size_t)b * NT * ND + d] - st.x) * st.y * P.n1g[d] + P.n1b[d];
                P.modv[idx] = inorm * (1.f + tanhf(gm)) + bt;
            }
            for (int idx = gid; idx < NB * 16; idx += NBLK * NTHR) {
                int b = idx >> 4, c = idx & 15;
                P.ae[idx] = P.moa[(size_t)b * NMOx + 1024 + c] + P.mob[(size_t)b * NMOx + 1024 + c]
                          + P.mcb2[1024 + c];
            }
        }
        grid_sync_dev();

        // P5: z partials = mod @ wkvae, K split 2 -> 544 tiles
        for (int it = wgg; it < 544; it += NWG) {
            int kh = it & 1, tile = it >> 1;
            int row0 = (tile / 17) * 32, n0 = (tile % 17) * 64;
            wg_gemm(wg, wgtid, As, Bs,
                    P.modv + kh * 256, ND, 0, nullptr, nullptr, nullptr,
                    P.wkvae + (size_t)(kh * 256) * NMOx, NMOx, NMOx,
                    kh ? P.zb : P.za, NMOx, row0, n0, 256);
        }
        grid_sync_dev();

        // P6: state update + fused read of next context
        {
            const float* qn; long qstride;
            if (t < NT - 1) { qn = P.Q + (size_t)(t + 1) * ND; qstride = (long)NT * ND; }
            else            { qn = P.Q + (size_t)NB * NT * ND; qstride = (long)ND; }
            for (int pair = wgg; pair < NB * NH; pair += NWG)
                wg_update_pair(wg, wgtid, As, pair, P, qn, qstride);
        }
        grid_sync_dev();
    }
}

// ---------------- host launcher ----------------

static void launch_gemm(const float* A, long lda, const float* Bm, long ldb, float* C, long ldc,
                        int M, int N, int K, int amode,
                        const float2* stats, const float* lng, const float* lnb,
                        const float* bias, int epi, const float* addm, long ldadd,
                        const float* A2 = nullptr, const float2* stats2 = nullptr) {
    GemmP p;
    p.A = A; p.lda = lda; p.A2 = A2; p.Bm = Bm; p.ldb = ldb; p.C = C; p.ldc = ldc;
    p.M = M; p.N = N; p.K = K; p.amode = amode;
    p.stats = stats; p.stats2 = stats2; p.lng = lng; p.lnb = lnb;
    p.bias = bias; p.epimode = epi; p.addm = addm; p.ldadd = ldadd;
    dim3 grid((N + 63) / 64, M / 64);
    gemm_tf32_kernel<<<grid, 128>>>(p);
}

extern "C" void kernel_launch(void* const* d_in, const int* in_sizes, int n_in,
                              void* d_out, int out_size) {
    const float* item  = (const float*)d_in[0];
    const float* ustat = (const float*)d_in[1];
    const float* lastI = (const float*)d_in[2];
    const float* init  = (const float*)d_in[3];
    const float* Wq    = (const float*)d_in[4];
    const float* Wk    = (const float*)d_in[5];
    const float* Wv    = (const float*)d_in[6];
    const float* Wa    = (const float*)d_in[7];
    const float* ba    = (const float*)d_in[8];
    const float* We    = (const float*)d_in[9];
    const float* be    = (const float*)d_in[10];
    const float* mcW1  = (const float*)d_in[11];
    const float* mcb1  = (const float*)d_in[12];
    const float* mcg   = (const float*)d_in[13];
    const float* mcbt  = (const float*)d_in[14];
    const float* mcW2  = (const float*)d_in[15];
    const float* mcb2  = (const float*)d_in[16];
    const float* Wo    = (const float*)d_in[17];
    const float* bo    = (const float*)d_in[18];
    const float* W1    = (const float*)d_in[19];
    const float* b1    = (const float*)d_in[20];
    const float* W2    = (const float*)d_in[21];
    const float* b2    = (const float*)d_in[22];
    const float* n1g   = (const float*)d_in[23];
    const float* n1b   = (const float*)d_in[24];
    const float* n2g   = (const float*)d_in[25];
    const float* n2b   = (const float*)d_in[26];
    float* out = (float*)d_out;

    float *state, *usnorm, *Q, *mctx, *y1p, *y1, *moa, *mob, *ae, *modv, *za, *zb, *wkvae, *x, *a1;
    float2 *istats, *lstats, *hstats, *xstats;
    cudaGetSymbolAddress((void**)&state,  g_state);
    cudaGetSymbolAddress((void**)&istats, g_istats);
    cudaGetSymbolAddress((void**)&lstats, g_lstats);
    cudaGetSymbolAddress((void**)&hstats, g_hstats);
    cudaGetSymbolAddress((void**)&xstats, g_xstats);
    cudaGetSymbolAddress((void**)&usnorm, g_usnorm);
    cudaGetSymbolAddress((void**)&Q,      g_Q);
    cudaGetSymbolAddress((void**)&mctx,   g_mctx);
    cudaGetSymbolAddress((void**)&y1p,    g_y1p);
    cudaGetSymbolAddress((void**)&y1,     g_y1);
    cudaGetSymbolAddress((void**)&moa,    g_moa);
    cudaGetSymbolAddress((void**)&mob,    g_mob);
    cudaGetSymbolAddress((void**)&ae,     g_ae);
    cudaGetSymbolAddress((void**)&modv,   g_mod);
    cudaGetSymbolAddress((void**)&za,     g_za);
    cudaGetSymbolAddress((void**)&zb,     g_zb);
    cudaGetSymbolAddress((void**)&wkvae,  g_wkvae);
    cudaGetSymbolAddress((void**)&x,      g_x);
    cudaGetSymbolAddress((void**)&a1,     g_a1);

    cudaFuncSetAttribute(recurrence_kernel, cudaFuncAttributeMaxDynamicSharedMemorySize, SMEM_BYTES);

    // ---- preamble (recurrence is the 6th kernel launch -> ncu -s 5 profiles it) ----
    ln_stats_all_kernel<<<NB * NT + NB, 128>>>(item, lastI, istats, lstats);     // 1
    ln_full_kernel<<<NB, 128>>>(ustat, n1g, n1b, usnorm, ND);                    // 2
    build_wkvae_kernel<<<2080, 256>>>(Wk, Wv, Wa, We, wkvae);                    // 3
    // Q (+qlast rows appended): LN(item|lastI) @ Wq                               4
    launch_gemm(item, ND, Wq, ND, Q, ND, NB * NT + NB, ND, ND, 3,
                istats, n1g, n1b, nullptr, 0, nullptr, 0, lastI, lstats);
    l2n_kernel<<<((NB * NT + NB) * NH) / 8, 256>>>(Q, (NB * NT + NB) * NH);      // 5

    // ---- full recurrence (incl. state init + initial read) ----                  6
    RecP P;
    P.item = item; P.istats = istats; P.usnorm = usnorm; P.mctx = mctx;
    P.Q = Q; P.init = init;
    P.y1p = y1p; P.y1 = y1; P.hstats = hstats;
    P.moa = moa; P.mob = mob; P.ae = ae; P.modv = modv;
    P.za = za; P.zb = zb; P.state = state;
    P.mcW1 = mcW1; P.mcb1 = mcb1; P.mcg = mcg; P.mcbt = mcbt;
    P.mcW2 = mcW2; P.mcb2 = mcb2; P.wkvae = wkvae;
    P.ba = ba; P.be = be; P.n1g = n1g; P.n1b = n1b;
    recurrence_kernel<<<NBLK, NTHR, SMEM_BYTES>>>(P);

    // ---- readout + FFN ----
    launch_gemm(mctx, ND, Wo, ND, x, ND, NB, ND, ND, 0,
                nullptr, nullptr, nullptr, bo, 2, ustat, ND);
    ln_stats_kernel<<<NB, 128>>>(x, xstats, ND);
    launch_gemm(x, ND, W1, NFF, a1, NFF, NB, NFF, ND, 1,
                xstats, n2g, n2b, b1, 1, nullptr, 0);
    launch_gemm(a1, NFF, W2, ND, out, ND, NB, ND, NFF, 0,
                nullptr, nullptr, nullptr, b2, 2, x, ND);
}